// round 10
// baseline (speedup 1.0000x reference)
#include <cuda_runtime.h>
#include <cstdint>

// ---------------- static scratch (no allocations allowed) ----------------
#define MAXN0 600000
__device__ float g_x0[MAXN0 * 16];
__device__ float g_x1[MAXN0 * 16];
__device__ float g_x2[MAXN0 * 32];
__device__ float g_r0[MAXN0 * 32];
__device__ float g_r1[MAXN0 * 32];
__device__ int   g_gi0[27 * MAXN0];
__device__ int   g_gid[8 * MAXN0];
__device__ int   g_gi1[27 * MAXN0];

typedef unsigned long long u64;
union F2U { u64 u; float2 f; };

__device__ __forceinline__ u64 bcast2(float s) {
    u64 r; asm("mov.b64 %0, {%1, %1};" : "=l"(r) : "r"(__float_as_uint(s))); return r;
}
__device__ __forceinline__ void ffma2(u64& a, u64 x, u64 w) {
    asm("fma.rn.f32x2 %0, %1, %2, %3;" : "=l"(a) : "l"(x), "l"(w), "l"(a));
}
__device__ __forceinline__ u64 packf2(float lo, float hi) {
    u64 r; asm("mov.b64 %0, {%1, %2};" : "=l"(r) : "r"(__float_as_uint(lo)), "r"(__float_as_uint(hi))); return r;
}
__device__ __forceinline__ void loadX4(float4* X, const float* x, int i, int rowf) {
    const float4* xr = (const float4*)(x + (size_t)(i < 0 ? 0 : i) * rowf);
#pragma unroll
    for (int q = 0; q < 4; ++q)
        X[q] = (i >= 0) ? __ldg(xr + q) : make_float4(0.f, 0.f, 0.f, 0.f);
}
__device__ __forceinline__ uint32_t smem_u32(const void* p) {
    uint32_t a;
    asm("{ .reg .u64 t; cvta.to.shared.u64 t, %1; cvt.u32.u64 %0, t; }" : "=r"(a) : "l"(p));
    return a;
}
__device__ __forceinline__ void cp_async16(uint32_t dst, const void* src) {
    asm volatile("cp.async.cg.shared.global [%0], [%1], 16;" :: "r"(dst), "l"(src) : "memory");
}
#define CP_COMMIT() asm volatile("cp.async.commit_group;" ::: "memory")
#define CP_WAIT1()  asm volatile("cp.async.wait_group 1;" ::: "memory")

// ---------------- inverse-map build ----------------
__global__ void build_gi(const int* __restrict__ kin, const int* __restrict__ kout,
                         int* __restrict__ gi, int P, int n) {
    const int k = blockIdx.y;
    int p = blockIdx.x * blockDim.x + threadIdx.x;
    if (p >= P) return;
    const size_t base = (size_t)k * P;
    int j = kout[base + p];
    if (j < n) gi[(size_t)k * n + j] = kin[base + p];
}

// ---------------- conv 1->16 (scalar, batched gather; R7) ---------------
__global__ __launch_bounds__(256) void conv1_16(const float* __restrict__ x,
        const float* __restrict__ W, const int* __restrict__ gi,
        const float* __restrict__ b, float* __restrict__ out,
        float* __restrict__ cache, int n) {
    __shared__ float Ws[27 * 16];
    for (int t = threadIdx.x; t < 27 * 16; t += 256) Ws[t] = W[t];
    __syncthreads();
    int j = blockIdx.x * 256 + threadIdx.x;
    if (j >= n) return;
    float acc[16];
#pragma unroll
    for (int c = 0; c < 16; ++c) acc[c] = __ldg(b + c);
#pragma unroll
    for (int kb = 0; kb < 27; kb += 9) {
        int idx[9];
#pragma unroll
        for (int t = 0; t < 9; ++t) idx[t] = __ldg(gi + (size_t)(kb + t) * n + j);
        float xv[9];
#pragma unroll
        for (int t = 0; t < 9; ++t) xv[t] = (idx[t] >= 0) ? __ldg(x + idx[t]) : 0.f;
#pragma unroll
        for (int t = 0; t < 9; ++t) {
#pragma unroll
            for (int c = 0; c < 16; ++c) acc[c] += xv[t] * Ws[(kb + t) * 16 + c];
        }
    }
    float4* o4 = (float4*)(out + (size_t)j * 16);
    float4* c4 = (float4*)(cache + (size_t)j * 16);
#pragma unroll
    for (int r = 0; r < 4; ++r) {
        float4 v = make_float4(fmaxf(acc[4*r], 0.f), fmaxf(acc[4*r+1], 0.f),
                               fmaxf(acc[4*r+2], 0.f), fmaxf(acc[4*r+3], 0.f));
        o4[r] = v; c4[r] = v;
    }
}

// ========= conv 16->16 (K=27): cp.async smem staging ====================
// smem: W 27*64 float4 (27648 B) + per-warp stages: 2 x 32 rows x 80 B.
static constexpr int C16_W     = 27 * 64 * 16;       // 27648
static constexpr int C16_ROWB  = 80;                  // 64B row + 16B pad
static constexpr int C16_STAGE = 32 * C16_ROWB;       // 2560
static constexpr int C16_SMEM  = C16_W + 8 * 2 * C16_STAGE;  // 68608

__global__ __launch_bounds__(256, 3) void conv16_16a(const float* __restrict__ x,
        const float* __restrict__ W, const int* __restrict__ gi,
        const float* __restrict__ b, float* __restrict__ out, int n) {
    extern __shared__ char smem[];
    float4* Ws4 = (float4*)smem;
    const float4* Wg = (const float4*)W;
    for (int t = threadIdx.x; t < 27 * 64; t += 256) Ws4[t] = Wg[t];
    __syncthreads();
    const ulonglong2* Wu = (const ulonglong2*)Ws4;
    const int tid = threadIdx.x, warp = tid >> 5, lane = tid & 31;
    const uint32_t stg = smem_u32(smem) + C16_W + warp * (2 * C16_STAGE) + lane * C16_ROWB;

    const int j = blockIdx.x * 256 + tid;
    const bool jv = j < n;
    u64 acc[8];
    {
        const float4* b4 = (const float4*)b;
#pragma unroll
        for (int r = 0; r < 4; ++r) {
            float4 bb = __ldg(b4 + r);
            acc[2*r] = packf2(bb.x, bb.y); acc[2*r+1] = packf2(bb.z, bb.w);
        }
    }
    int i1 = jv ? __ldg(gi + j) : -1;                    // gi[k]
    int i2 = jv ? __ldg(gi + (size_t)n + j) : -1;        // gi[k+1]
    {   // prologue: stage 0 <- row i1
        const char* src = (const char*)(x + (size_t)(i1 < 0 ? 0 : i1) * 16);
#pragma unroll
        for (int q = 0; q < 4; ++q) cp_async16(stg + q * 16, src + q * 16);
        CP_COMMIT();
    }
    for (int k = 0; k < 27; ++k) {
        int i3 = (k < 25 && jv) ? __ldg(gi + (size_t)(k + 2) * n + j) : -1;
        {   // issue stage k+1 <- row i2
            const char* src = (const char*)(x + (size_t)(i2 < 0 ? 0 : i2) * 16);
            uint32_t d = stg + (((k + 1) & 1) ? C16_STAGE : 0);
#pragma unroll
            for (int q = 0; q < 4; ++q) cp_async16(d + q * 16, src + q * 16);
            CP_COMMIT();
        }
        CP_WAIT1();                                       // stage k ready
        const int ik = i1;
        i1 = i2; i2 = i3;
        if (__ballot_sync(0xffffffffu, ik >= 0)) {
            const char* myrow = (const char*)smem + (stg - smem_u32(smem)) + ((k & 1) ? C16_STAGE : 0);
            float4 X[4];
#pragma unroll
            for (int q = 0; q < 4; ++q)
                X[q] = (ik >= 0) ? *(const float4*)(myrow + q * 16)
                                 : make_float4(0.f, 0.f, 0.f, 0.f);
            const ulonglong2* Wk = Wu + (size_t)k * 64;
#pragma unroll
            for (int q = 0; q < 4; ++q) {
                float xs[4] = {X[q].x, X[q].y, X[q].z, X[q].w};
#pragma unroll
                for (int s = 0; s < 4; ++s) {
                    int cc = q * 4 + s;
                    u64 xx = bcast2(xs[s]);
#pragma unroll
                    for (int r = 0; r < 4; ++r) {
                        ulonglong2 wp = Wk[cc * 4 + r];
                        ffma2(acc[2*r],     xx, wp.x);
                        ffma2(acc[2*r + 1], xx, wp.y);
                    }
                }
            }
        }
    }
    if (jv) {
        float4* o4 = (float4*)(out + (size_t)j * 16);
#pragma unroll
        for (int r = 0; r < 4; ++r) {
            F2U a0, a1; a0.u = acc[2*r]; a1.u = acc[2*r+1];
            o4[r] = make_float4(fmaxf(a0.f.x, 0.f), fmaxf(a0.f.y, 0.f),
                                fmaxf(a1.f.x, 0.f), fmaxf(a1.f.y, 0.f));
        }
    }
}

// ---------------- conv 16->32 (K=8, scalar, pipelined; R7) --------------
__global__ __launch_bounds__(256, 3) void conv16_32(const float* __restrict__ x,
        const float* __restrict__ W, const int* __restrict__ gi,
        const float* __restrict__ b, float* __restrict__ out, int n) {
    __shared__ float4 Ws4[8 * 128];
    const float4* Wg = (const float4*)W;
    for (int t = threadIdx.x; t < 8 * 128; t += 256) Ws4[t] = Wg[t];
    __syncthreads();
    const ulonglong2* Wu = (const ulonglong2*)Ws4;
    int j = blockIdx.x * 256 + threadIdx.x;
    bool jv = j < n;
    u64 acc[16];
    {
        const float4* b4 = (const float4*)b;
#pragma unroll
        for (int r = 0; r < 8; ++r) {
            float4 bb = __ldg(b4 + r);
            acc[2*r] = packf2(bb.x, bb.y); acc[2*r+1] = packf2(bb.z, bb.w);
        }
    }
    int icur = jv ? __ldg(gi + j) : -1;
    float4 Xn[4];
    loadX4(Xn, x, icur, 16);
    for (int k = 0; k < 8; ++k) {
        float4 Xc[4];
#pragma unroll
        for (int q = 0; q < 4; ++q) Xc[q] = Xn[q];
        int iprev = icur;
        icur = (k < 7 && jv) ? __ldg(gi + (size_t)(k + 1) * n + j) : -1;
        loadX4(Xn, x, icur, 16);
        if (!__ballot_sync(0xffffffffu, iprev >= 0)) continue;
        const ulonglong2* Wk = Wu + (size_t)k * 128;
#pragma unroll
        for (int q = 0; q < 4; ++q) {
            float xs[4] = {Xc[q].x, Xc[q].y, Xc[q].z, Xc[q].w};
#pragma unroll
            for (int s = 0; s < 4; ++s) {
                int cc = q * 4 + s;
                u64 xx = bcast2(xs[s]);
#pragma unroll
                for (int r = 0; r < 8; ++r) {
                    ulonglong2 wp = Wk[cc * 8 + r];
                    ffma2(acc[2*r],     xx, wp.x);
                    ffma2(acc[2*r + 1], xx, wp.y);
                }
            }
        }
    }
    if (jv) {
        float4* o4 = (float4*)(out + (size_t)j * 32);
#pragma unroll
        for (int r = 0; r < 8; ++r) {
            F2U a0, a1; a0.u = acc[2*r]; a1.u = acc[2*r+1];
            o4[r] = make_float4(fmaxf(a0.f.x, 0.f), fmaxf(a0.f.y, 0.f),
                                fmaxf(a1.f.x, 0.f), fmaxf(a1.f.y, 0.f));
        }
    }
}

// ========= conv 32->32 (K=27): cp.async smem staging ====================
// smem: W 27*256 float4 (110592 B) + per-warp stages: 2 x 32 rows x 144 B.
static constexpr int C32_W     = 27 * 256 * 16;      // 110592
static constexpr int C32_ROWB  = 144;                 // 128B row + 16B pad
static constexpr int C32_STAGE = 32 * C32_ROWB;       // 4608
static constexpr int C32_SMEM  = C32_W + 8 * 2 * C32_STAGE;  // 184320

template <int EPI>   // 0 = bias+relu, 1 = bias+residual, 2 = bias only
__global__ __launch_bounds__(256) void conv32_32a(const float* __restrict__ x,
        const float* __restrict__ W, const int* __restrict__ gi,
        const float* __restrict__ b, const float* __restrict__ skip,
        float* __restrict__ out, int n) {
    extern __shared__ char smem[];
    float4* Ws4 = (float4*)smem;
    const float4* Wg = (const float4*)W;
    for (int t = threadIdx.x; t < 27 * 256; t += 256) Ws4[t] = Wg[t];
    __syncthreads();
    const ulonglong2* Wu = (const ulonglong2*)Ws4;
    const int tid = threadIdx.x, warp = tid >> 5, lane = tid & 31;
    const uint32_t stgbase = C32_W + warp * (2 * C32_STAGE) + lane * C32_ROWB;
    const uint32_t stg = smem_u32(smem) + stgbase;

    const int j = blockIdx.x * 256 + tid;
    const bool jv = j < n;
    u64 acc[16];
    {
        const float4* b4 = (const float4*)b;
#pragma unroll
        for (int r = 0; r < 8; ++r) {
            float4 bb = __ldg(b4 + r);
            acc[2*r] = packf2(bb.x, bb.y); acc[2*r+1] = packf2(bb.z, bb.w);
        }
    }
    int i1 = jv ? __ldg(gi + j) : -1;                    // gi[k]
    int i2 = jv ? __ldg(gi + (size_t)n + j) : -1;        // gi[k+1]
    {   // prologue: stage 0 <- row i1
        const char* src = (const char*)(x + (size_t)(i1 < 0 ? 0 : i1) * 32);
#pragma unroll
        for (int q = 0; q < 8; ++q) cp_async16(stg + q * 16, src + q * 16);
        CP_COMMIT();
    }
    for (int k = 0; k < 27; ++k) {
        int i3 = (k < 25 && jv) ? __ldg(gi + (size_t)(k + 2) * n + j) : -1;
        {   // issue stage k+1 <- row i2
            const char* src = (const char*)(x + (size_t)(i2 < 0 ? 0 : i2) * 32);
            uint32_t d = stg + (((k + 1) & 1) ? C32_STAGE : 0);
#pragma unroll
            for (int q = 0; q < 8; ++q) cp_async16(d + q * 16, src + q * 16);
            CP_COMMIT();
        }
        CP_WAIT1();                                       // stage k ready
        const int ik = i1;
        i1 = i2; i2 = i3;
        if (__ballot_sync(0xffffffffu, ik >= 0)) {
            const char* myrow = (const char*)smem + stgbase + ((k & 1) ? C32_STAGE : 0);
            float4 X[8];
#pragma unroll
            for (int q = 0; q < 8; ++q)
                X[q] = (ik >= 0) ? *(const float4*)(myrow + q * 16)
                                 : make_float4(0.f, 0.f, 0.f, 0.f);
            const ulonglong2* Wk = Wu + (size_t)k * 256;
#pragma unroll
            for (int q = 0; q < 8; ++q) {
                float xs[4] = {X[q].x, X[q].y, X[q].z, X[q].w};
#pragma unroll
                for (int s = 0; s < 4; ++s) {
                    int cc = q * 4 + s;
                    u64 xx = bcast2(xs[s]);
#pragma unroll
                    for (int r = 0; r < 8; ++r) {
                        ulonglong2 wp = Wk[cc * 8 + r];
                        ffma2(acc[2*r],     xx, wp.x);
                        ffma2(acc[2*r + 1], xx, wp.y);
                    }
                }
            }
        }
    }
    if (jv) {
        float4* o4 = (float4*)(out + (size_t)j * 32);
        const float4* s4 = (EPI == 1) ? (const float4*)(skip + (size_t)j * 32) : nullptr;
#pragma unroll
        for (int r = 0; r < 8; ++r) {
            F2U a0, a1; a0.u = acc[2*r]; a1.u = acc[2*r+1];
            float4 v = make_float4(a0.f.x, a0.f.y, a1.f.x, a1.f.y);
            if (EPI == 0) {
                v.x = fmaxf(v.x, 0.f); v.y = fmaxf(v.y, 0.f);
                v.z = fmaxf(v.z, 0.f); v.w = fmaxf(v.w, 0.f);
            }
            if (EPI == 1) {
                float4 sv = __ldg(s4 + r);
                v.x += sv.x; v.y += sv.y; v.z += sv.z; v.w += sv.w;
            }
            o4[r] = v;
        }
    }
}

// ---------------- host orchestration ----------------
extern "C" void kernel_launch(void* const* d_in, const int* in_sizes, int n_in,
                              void* d_out, int out_size) {
    const float* in_feats = (const float*)d_in[0];
    const float* W_first  = (const float*)d_in[1];
    const float* b_first  = (const float*)d_in[2];
    const float* W_pre    = (const float*)d_in[3];
    const float* b_pre    = (const float*)d_in[4];
    const float* W_down   = (const float*)d_in[5];
    const float* b_down   = (const float*)d_in[6];
    const float* W_r0     = (const float*)d_in[7];
    const float* b_r0     = (const float*)d_in[8];
    const float* W_r1     = (const float*)d_in[9];
    const float* b_r1     = (const float*)d_in[10];
    const float* W_fin    = (const float*)d_in[11];
    const float* b_fin    = (const float*)d_in[12];
    const int* km0_in  = (const int*)d_in[13];
    const int* km0_out = (const int*)d_in[14];
    const int* kmd_in  = (const int*)d_in[15];
    const int* kmd_out = (const int*)d_in[16];
    const int* km1_in  = (const int*)d_in[17];
    const int* km1_out = (const int*)d_in[18];

    const int n0 = in_sizes[0];
    const int P0 = in_sizes[13] / 27;
    const int Pd = in_sizes[15] / 8;
    const int P1 = in_sizes[17] / 27;
    const int n1 = (out_size - n0 * 16) / 32;

    float* out_fin    = (float*)d_out;
    float* out_cached = (float*)d_out + (size_t)n1 * 32;

    float *x0, *x1, *x2, *r0, *r1;
    int *gi0, *gid, *gi1;
    cudaGetSymbolAddress((void**)&x0, g_x0);
    cudaGetSymbolAddress((void**)&x1, g_x1);
    cudaGetSymbolAddress((void**)&x2, g_x2);
    cudaGetSymbolAddress((void**)&r0, g_r0);
    cudaGetSymbolAddress((void**)&r1, g_r1);
    cudaGetSymbolAddress((void**)&gi0, g_gi0);
    cudaGetSymbolAddress((void**)&gid, g_gid);
    cudaGetSymbolAddress((void**)&gi1, g_gi1);

    static bool attr_done = false;
    if (!attr_done) {
        cudaFuncSetAttribute(conv16_16a,    cudaFuncAttributeMaxDynamicSharedMemorySize, C16_SMEM);
        cudaFuncSetAttribute(conv32_32a<0>, cudaFuncAttributeMaxDynamicSharedMemorySize, C32_SMEM);
        cudaFuncSetAttribute(conv32_32a<1>, cudaFuncAttributeMaxDynamicSharedMemorySize, C32_SMEM);
        cudaFuncSetAttribute(conv32_32a<2>, cudaFuncAttributeMaxDynamicSharedMemorySize, C32_SMEM);
        attr_done = true;
    }

    auto ceil_div = [](int a, int b) { return (a + b - 1) / b; };
    const int T = 256;

    // ---- build inverse maps ----
    cudaMemsetAsync(gi0, 0xFF, (size_t)27 * n0 * sizeof(int), 0);
    cudaMemsetAsync(gid, 0xFF, (size_t)8 * n1 * sizeof(int), 0);
    cudaMemsetAsync(gi1, 0xFF, (size_t)27 * n1 * sizeof(int), 0);
    {
        dim3 g0(ceil_div(P0, T), 27);
        build_gi<<<g0, T>>>(km0_in, km0_out, gi0, P0, n0);
        dim3 gd(ceil_div(Pd, T), 8);
        build_gi<<<gd, T>>>(kmd_in, kmd_out, gid, Pd, n1);
        dim3 g1(ceil_div(P1, T), 27);
        build_gi<<<g1, T>>>(km1_in, km1_out, gi1, P1, n1);
    }

    conv1_16<<<ceil_div(n0, T), T>>>(in_feats, W_first, gi0, b_first, x0, out_cached, n0);
    conv16_16a<<<ceil_div(n0, T), T, C16_SMEM>>>(x0, W_pre, gi0, b_pre, x1, n0);
    conv16_32<<<ceil_div(n1, T), T>>>(x1, W_down, gid, b_down, x2, n1);

    const int gb = ceil_div(n1, 256);
    conv32_32a<0><<<gb, 256, C32_SMEM>>>(x2, W_r0, gi1, b_r0, nullptr, r0, n1);
    conv32_32a<1><<<gb, 256, C32_SMEM>>>(r0, W_r1, gi1, b_r1, x2, r1, n1);
    conv32_32a<2><<<gb, 256, C32_SMEM>>>(r1, W_fin, gi1, b_fin, nullptr, out_fin, n1);
}

// round 11
// speedup vs baseline: 26.9515x; 26.9515x over previous
#include <cuda_runtime.h>
#include <cstdint>

// ---------------- static scratch (no allocations allowed) ----------------
#define MAXN0 600000
__device__ float g_x0[MAXN0 * 16];
__device__ float g_x1[MAXN0 * 16];
__device__ float g_x2[MAXN0 * 32];
__device__ float g_r0[MAXN0 * 32];
__device__ float g_r1[MAXN0 * 32];
__device__ int   g_gi0[27 * MAXN0];
__device__ int   g_gid[8 * MAXN0];
__device__ int   g_gi1[27 * MAXN0];

typedef unsigned long long u64;
union F2U { u64 u; float2 f; };

__device__ __forceinline__ u64 bcast2(float s) {
    u64 r; asm("mov.b64 %0, {%1, %1};" : "=l"(r) : "r"(__float_as_uint(s))); return r;
}
__device__ __forceinline__ void ffma2(u64& a, u64 x, u64 w) {
    asm("fma.rn.f32x2 %0, %1, %2, %3;" : "=l"(a) : "l"(x), "l"(w), "l"(a));
}
__device__ __forceinline__ u64 packf2(float lo, float hi) {
    u64 r; asm("mov.b64 %0, {%1, %2};" : "=l"(r) : "r"(__float_as_uint(lo)), "r"(__float_as_uint(hi))); return r;
}
__device__ __forceinline__ void loadX4(float4* X, const float* x, int i, int rowf) {
    const float4* xr = (const float4*)(x + (size_t)(i < 0 ? 0 : i) * rowf);
#pragma unroll
    for (int q = 0; q < 4; ++q)
        X[q] = (i >= 0) ? __ldg(xr + q) : make_float4(0.f, 0.f, 0.f, 0.f);
}

// ---------------- inverse-map build ----------------
__global__ void build_gi(const int* __restrict__ kin, const int* __restrict__ kout,
                         int* __restrict__ gi, int P, int n) {
    const int k = blockIdx.y;
    int p = blockIdx.x * blockDim.x + threadIdx.x;
    if (p >= P) return;
    const size_t base = (size_t)k * P;
    int j = kout[base + p];
    if (j < n) gi[(size_t)k * n + j] = kin[base + p];
}

// ---------------- conv 1->16 (scalar, batched gather; R7) ---------------
__global__ __launch_bounds__(256) void conv1_16(const float* __restrict__ x,
        const float* __restrict__ W, const int* __restrict__ gi,
        const float* __restrict__ b, float* __restrict__ out,
        float* __restrict__ cache, int n) {
    __shared__ float Ws[27 * 16];
    for (int t = threadIdx.x; t < 27 * 16; t += 256) Ws[t] = W[t];
    __syncthreads();
    int j = blockIdx.x * 256 + threadIdx.x;
    if (j >= n) return;
    float acc[16];
#pragma unroll
    for (int c = 0; c < 16; ++c) acc[c] = __ldg(b + c);
#pragma unroll
    for (int kb = 0; kb < 27; kb += 9) {
        int idx[9];
#pragma unroll
        for (int t = 0; t < 9; ++t) idx[t] = __ldg(gi + (size_t)(kb + t) * n + j);
        float xv[9];
#pragma unroll
        for (int t = 0; t < 9; ++t) xv[t] = (idx[t] >= 0) ? __ldg(x + idx[t]) : 0.f;
#pragma unroll
        for (int t = 0; t < 9; ++t) {
#pragma unroll
            for (int c = 0; c < 16; ++c) acc[c] += xv[t] * Ws[(kb + t) * 16 + c];
        }
    }
    float4* o4 = (float4*)(out + (size_t)j * 16);
    float4* c4 = (float4*)(cache + (size_t)j * 16);
#pragma unroll
    for (int r = 0; r < 4; ++r) {
        float4 v = make_float4(fmaxf(acc[4*r], 0.f), fmaxf(acc[4*r+1], 0.f),
                               fmaxf(acc[4*r+2], 0.f), fmaxf(acc[4*r+3], 0.f));
        o4[r] = v; c4[r] = v;
    }
}

// ---------------- conv 16->16 (K=27, scalar, pipelined; R7 verbatim) ----
__global__ __launch_bounds__(256, 4) void conv16_16(const float* __restrict__ x,
        const float* __restrict__ W, const int* __restrict__ gi,
        const float* __restrict__ b, float* __restrict__ out, int n) {
    __shared__ float4 Ws4[27 * 64];
    const float4* Wg = (const float4*)W;
    for (int t = threadIdx.x; t < 27 * 64; t += 256) Ws4[t] = Wg[t];
    __syncthreads();
    const ulonglong2* Wu = (const ulonglong2*)Ws4;
    int j = blockIdx.x * 256 + threadIdx.x;
    bool jv = j < n;
    u64 acc[8];
    {
        const float4* b4 = (const float4*)b;
#pragma unroll
        for (int r = 0; r < 4; ++r) {
            float4 bb = __ldg(b4 + r);
            acc[2*r] = packf2(bb.x, bb.y); acc[2*r+1] = packf2(bb.z, bb.w);
        }
    }
    int icur = jv ? __ldg(gi + j) : -1;
    float4 Xn[4];
    loadX4(Xn, x, icur, 16);
    for (int k = 0; k < 27; ++k) {
        float4 Xc[4];
#pragma unroll
        for (int q = 0; q < 4; ++q) Xc[q] = Xn[q];
        int iprev = icur;
        icur = (k < 26 && jv) ? __ldg(gi + (size_t)(k + 1) * n + j) : -1;
        loadX4(Xn, x, icur, 16);
        if (!__ballot_sync(0xffffffffu, iprev >= 0)) continue;
        const ulonglong2* Wk = Wu + (size_t)k * 64;
#pragma unroll
        for (int q = 0; q < 4; ++q) {
            float xs[4] = {Xc[q].x, Xc[q].y, Xc[q].z, Xc[q].w};
#pragma unroll
            for (int s = 0; s < 4; ++s) {
                int cc = q * 4 + s;
                u64 xx = bcast2(xs[s]);
#pragma unroll
                for (int r = 0; r < 4; ++r) {
                    ulonglong2 wp = Wk[cc * 4 + r];
                    ffma2(acc[2*r],     xx, wp.x);
                    ffma2(acc[2*r + 1], xx, wp.y);
                }
            }
        }
    }
    if (jv) {
        float4* o4 = (float4*)(out + (size_t)j * 16);
#pragma unroll
        for (int r = 0; r < 4; ++r) {
            F2U a0, a1; a0.u = acc[2*r]; a1.u = acc[2*r+1];
            o4[r] = make_float4(fmaxf(a0.f.x, 0.f), fmaxf(a0.f.y, 0.f),
                                fmaxf(a1.f.x, 0.f), fmaxf(a1.f.y, 0.f));
        }
    }
}

// ---------------- conv 16->32 (K=8, scalar, pipelined; R7 verbatim) -----
__global__ __launch_bounds__(256, 3) void conv16_32(const float* __restrict__ x,
        const float* __restrict__ W, const int* __restrict__ gi,
        const float* __restrict__ b, float* __restrict__ out, int n) {
    __shared__ float4 Ws4[8 * 128];
    const float4* Wg = (const float4*)W;
    for (int t = threadIdx.x; t < 8 * 128; t += 256) Ws4[t] = Wg[t];
    __syncthreads();
    const ulonglong2* Wu = (const ulonglong2*)Ws4;
    int j = blockIdx.x * 256 + threadIdx.x;
    bool jv = j < n;
    u64 acc[16];
    {
        const float4* b4 = (const float4*)b;
#pragma unroll
        for (int r = 0; r < 8; ++r) {
            float4 bb = __ldg(b4 + r);
            acc[2*r] = packf2(bb.x, bb.y); acc[2*r+1] = packf2(bb.z, bb.w);
        }
    }
    int icur = jv ? __ldg(gi + j) : -1;
    float4 Xn[4];
    loadX4(Xn, x, icur, 16);
    for (int k = 0; k < 8; ++k) {
        float4 Xc[4];
#pragma unroll
        for (int q = 0; q < 4; ++q) Xc[q] = Xn[q];
        int iprev = icur;
        icur = (k < 7 && jv) ? __ldg(gi + (size_t)(k + 1) * n + j) : -1;
        loadX4(Xn, x, icur, 16);
        if (!__ballot_sync(0xffffffffu, iprev >= 0)) continue;
        const ulonglong2* Wk = Wu + (size_t)k * 128;
#pragma unroll
        for (int q = 0; q < 4; ++q) {
            float xs[4] = {Xc[q].x, Xc[q].y, Xc[q].z, Xc[q].w};
#pragma unroll
            for (int s = 0; s < 4; ++s) {
                int cc = q * 4 + s;
                u64 xx = bcast2(xs[s]);
#pragma unroll
                for (int r = 0; r < 8; ++r) {
                    ulonglong2 wp = Wk[cc * 8 + r];
                    ffma2(acc[2*r],     xx, wp.x);
                    ffma2(acc[2*r + 1], xx, wp.y);
                }
            }
        }
    }
    if (jv) {
        float4* o4 = (float4*)(out + (size_t)j * 32);
#pragma unroll
        for (int r = 0; r < 8; ++r) {
            F2U a0, a1; a0.u = acc[2*r]; a1.u = acc[2*r+1];
            o4[r] = make_float4(fmaxf(a0.f.x, 0.f), fmaxf(a0.f.y, 0.f),
                                fmaxf(a1.f.x, 0.f), fmaxf(a1.f.y, 0.f));
        }
    }
}

// ====== conv 32->32 (K=27): two output rows per thread (weight reuse) ===
// Per k per warp: 256 broadcast LDS.128 serve 1024 FFMA2 (2 rows/lane).
template <int EPI>   // 0 = bias+relu, 1 = bias+residual, 2 = bias only
__global__ __launch_bounds__(256) void conv32_32j2(const float* __restrict__ x,
        const float* __restrict__ W, const int* __restrict__ gi,
        const float* __restrict__ b, const float* __restrict__ skip,
        float* __restrict__ out, int n) {
    extern __shared__ float4 Ws4[];          // 27 * 256 float4 = 108 KB
    const float4* Wg = (const float4*)W;
    for (int t = threadIdx.x; t < 27 * 256; t += 256) Ws4[t] = Wg[t];
    __syncthreads();
    const ulonglong2* Wu = (const ulonglong2*)Ws4;
    const int tid = threadIdx.x;
    const int j0 = blockIdx.x * 512 + tid;
    const int j1 = j0 + 256;
    const bool jv0 = j0 < n, jv1 = j1 < n;

    u64 acc[32];                              // [0..15] row j0, [16..31] row j1
    {
        const float4* b4 = (const float4*)b;
#pragma unroll
        for (int r = 0; r < 8; ++r) {
            float4 bb = __ldg(b4 + r);
            u64 lo = packf2(bb.x, bb.y), hi = packf2(bb.z, bb.w);
            acc[2*r] = lo; acc[2*r+1] = hi;
            acc[16 + 2*r] = lo; acc[16 + 2*r+1] = hi;
        }
    }
    int a0 = jv0 ? __ldg(gi + j0) : -1;
    int a1 = jv1 ? __ldg(gi + j1) : -1;
    for (int k = 0; k < 27; ++k) {
        const int i0 = a0, i1 = a1;
        a0 = (k < 26 && jv0) ? __ldg(gi + (size_t)(k + 1) * n + j0) : -1;
        a1 = (k < 26 && jv1) ? __ldg(gi + (size_t)(k + 1) * n + j1) : -1;
        if (!__ballot_sync(0xffffffffu, (i0 >= 0) || (i1 >= 0))) continue;
        const float4* xr0 = (const float4*)(x + (size_t)(i0 < 0 ? 0 : i0) * 32);
        const float4* xr1 = (const float4*)(x + (size_t)(i1 < 0 ? 0 : i1) * 32);
        const ulonglong2* Wk = Wu + (size_t)k * 256;
#pragma unroll
        for (int h = 0; h < 2; ++h) {         // input-channel halves keep regs low
            float4 X0[4], X1[4];
#pragma unroll
            for (int q = 0; q < 4; ++q) {
                X0[q] = (i0 >= 0) ? __ldg(xr0 + h * 4 + q) : make_float4(0.f, 0.f, 0.f, 0.f);
                X1[q] = (i1 >= 0) ? __ldg(xr1 + h * 4 + q) : make_float4(0.f, 0.f, 0.f, 0.f);
            }
#pragma unroll
            for (int q = 0; q < 4; ++q) {
                float xs0[4] = {X0[q].x, X0[q].y, X0[q].z, X0[q].w};
                float xs1[4] = {X1[q].x, X1[q].y, X1[q].z, X1[q].w};
#pragma unroll
                for (int s = 0; s < 4; ++s) {
                    int cc = h * 16 + q * 4 + s;
                    u64 xx0 = bcast2(xs0[s]);
                    u64 xx1 = bcast2(xs1[s]);
#pragma unroll
                    for (int r = 0; r < 8; ++r) {
                        ulonglong2 wp = Wk[cc * 8 + r];
                        ffma2(acc[2*r],          xx0, wp.x);
                        ffma2(acc[2*r + 1],      xx0, wp.y);
                        ffma2(acc[16 + 2*r],     xx1, wp.x);
                        ffma2(acc[16 + 2*r + 1], xx1, wp.y);
                    }
                }
            }
        }
    }
#pragma unroll
    for (int o = 0; o < 2; ++o) {
        const int j = o ? j1 : j0;
        if (j >= n) continue;
        const u64* a = acc + o * 16;
        float4* o4 = (float4*)(out + (size_t)j * 32);
        const float4* s4 = (EPI == 1) ? (const float4*)(skip + (size_t)j * 32) : nullptr;
#pragma unroll
        for (int r = 0; r < 8; ++r) {
            F2U a0u, a1u; a0u.u = a[2*r]; a1u.u = a[2*r+1];
            float4 v = make_float4(a0u.f.x, a0u.f.y, a1u.f.x, a1u.f.y);
            if (EPI == 0) {
                v.x = fmaxf(v.x, 0.f); v.y = fmaxf(v.y, 0.f);
                v.z = fmaxf(v.z, 0.f); v.w = fmaxf(v.w, 0.f);
            }
            if (EPI == 1) {
                float4 sv = __ldg(s4 + r);
                v.x += sv.x; v.y += sv.y; v.z += sv.z; v.w += sv.w;
            }
            o4[r] = v;
        }
    }
}

// ---------------- host orchestration ----------------
extern "C" void kernel_launch(void* const* d_in, const int* in_sizes, int n_in,
                              void* d_out, int out_size) {
    const float* in_feats = (const float*)d_in[0];
    const float* W_first  = (const float*)d_in[1];
    const float* b_first  = (const float*)d_in[2];
    const float* W_pre    = (const float*)d_in[3];
    const float* b_pre    = (const float*)d_in[4];
    const float* W_down   = (const float*)d_in[5];
    const float* b_down   = (const float*)d_in[6];
    const float* W_r0     = (const float*)d_in[7];
    const float* b_r0     = (const float*)d_in[8];
    const float* W_r1     = (const float*)d_in[9];
    const float* b_r1     = (const float*)d_in[10];
    const float* W_fin    = (const float*)d_in[11];
    const float* b_fin    = (const float*)d_in[12];
    const int* km0_in  = (const int*)d_in[13];
    const int* km0_out = (const int*)d_in[14];
    const int* kmd_in  = (const int*)d_in[15];
    const int* kmd_out = (const int*)d_in[16];
    const int* km1_in  = (const int*)d_in[17];
    const int* km1_out = (const int*)d_in[18];

    const int n0 = in_sizes[0];
    const int P0 = in_sizes[13] / 27;
    const int Pd = in_sizes[15] / 8;
    const int P1 = in_sizes[17] / 27;
    const int n1 = (out_size - n0 * 16) / 32;

    float* out_fin    = (float*)d_out;
    float* out_cached = (float*)d_out + (size_t)n1 * 32;

    float *x0, *x1, *x2, *r0, *r1;
    int *gi0, *gid, *gi1;
    cudaGetSymbolAddress((void**)&x0, g_x0);
    cudaGetSymbolAddress((void**)&x1, g_x1);
    cudaGetSymbolAddress((void**)&x2, g_x2);
    cudaGetSymbolAddress((void**)&r0, g_r0);
    cudaGetSymbolAddress((void**)&r1, g_r1);
    cudaGetSymbolAddress((void**)&gi0, g_gi0);
    cudaGetSymbolAddress((void**)&gid, g_gid);
    cudaGetSymbolAddress((void**)&gi1, g_gi1);

    const int SMEM32 = 27 * 256 * sizeof(float4);  // 110592 B
    static bool attr_done = false;
    if (!attr_done) {
        cudaFuncSetAttribute(conv32_32j2<0>, cudaFuncAttributeMaxDynamicSharedMemorySize, SMEM32);
        cudaFuncSetAttribute(conv32_32j2<1>, cudaFuncAttributeMaxDynamicSharedMemorySize, SMEM32);
        cudaFuncSetAttribute(conv32_32j2<2>, cudaFuncAttributeMaxDynamicSharedMemorySize, SMEM32);
        attr_done = true;
    }

    auto ceil_div = [](int a, int b) { return (a + b - 1) / b; };
    const int T = 256;

    // ---- build inverse maps ----
    cudaMemsetAsync(gi0, 0xFF, (size_t)27 * n0 * sizeof(int), 0);
    cudaMemsetAsync(gid, 0xFF, (size_t)8 * n1 * sizeof(int), 0);
    cudaMemsetAsync(gi1, 0xFF, (size_t)27 * n1 * sizeof(int), 0);
    {
        dim3 g0(ceil_div(P0, T), 27);
        build_gi<<<g0, T>>>(km0_in, km0_out, gi0, P0, n0);
        dim3 gd(ceil_div(Pd, T), 8);
        build_gi<<<gd, T>>>(kmd_in, kmd_out, gid, Pd, n1);
        dim3 g1(ceil_div(P1, T), 27);
        build_gi<<<g1, T>>>(km1_in, km1_out, gi1, P1, n1);
    }

    conv1_16<<<ceil_div(n0, T), T>>>(in_feats, W_first, gi0, b_first, x0, out_cached, n0);
    conv16_16<<<ceil_div(n0, T), T>>>(x0, W_pre, gi0, b_pre, x1, n0);
    conv16_32<<<ceil_div(n1, T), T>>>(x1, W_down, gid, b_down, x2, n1);

    const int gb = ceil_div(n1, 512);
    conv32_32j2<0><<<gb, 256, SMEM32>>>(x2, W_r0, gi1, b_r0, nullptr, r0, n1);
    conv32_32j2<1><<<gb, 256, SMEM32>>>(r0, W_r1, gi1, b_r1, x2, r1, n1);
    conv32_32j2<2><<<gb, 256, SMEM32>>>(r1, W_fin, gi1, b_fin, nullptr, out_fin, n1);
}

// round 12
// speedup vs baseline: 28.2341x; 1.0476x over previous
#include <cuda_runtime.h>
#include <cstdint>

// ---------------- static scratch (no allocations allowed) ----------------
#define MAXN0 600000
__device__ float g_x0[MAXN0 * 16];
__device__ float g_x1[MAXN0 * 16];
__device__ float g_x2[MAXN0 * 32];
__device__ float g_r0[MAXN0 * 32];
__device__ float g_r1[MAXN0 * 32];
__device__ int   g_gi0[27 * MAXN0];
__device__ int   g_gid[8 * MAXN0];
__device__ int   g_gi1[27 * MAXN0];

typedef unsigned long long u64;
union F2U { u64 u; float2 f; };

__device__ __forceinline__ u64 bcast2(float s) {
    u64 r; asm("mov.b64 %0, {%1, %1};" : "=l"(r) : "r"(__float_as_uint(s))); return r;
}
__device__ __forceinline__ void ffma2(u64& a, u64 x, u64 w) {
    asm("fma.rn.f32x2 %0, %1, %2, %3;" : "=l"(a) : "l"(x), "l"(w), "l"(a));
}
__device__ __forceinline__ u64 packf2(float lo, float hi) {
    u64 r; asm("mov.b64 %0, {%1, %2};" : "=l"(r) : "r"(__float_as_uint(lo)), "r"(__float_as_uint(hi))); return r;
}

// ---------------- inverse-map build ----------------
__global__ void build_gi(const int* __restrict__ kin, const int* __restrict__ kout,
                         int* __restrict__ gi, int P, int n) {
    const int k = blockIdx.y;
    int p = blockIdx.x * blockDim.x + threadIdx.x;
    if (p >= P) return;
    const size_t base = (size_t)k * P;
    int j = kout[base + p];
    if (j < n) gi[(size_t)k * n + j] = kin[base + p];
}

// ---------------- conv 1->16 (scalar, batched gather; R7) ---------------
__global__ __launch_bounds__(256) void conv1_16(const float* __restrict__ x,
        const float* __restrict__ W, const int* __restrict__ gi,
        const float* __restrict__ b, float* __restrict__ out,
        float* __restrict__ cache, int n) {
    __shared__ float Ws[27 * 16];
    for (int t = threadIdx.x; t < 27 * 16; t += 256) Ws[t] = W[t];
    __syncthreads();
    int j = blockIdx.x * 256 + threadIdx.x;
    if (j >= n) return;
    float acc[16];
#pragma unroll
    for (int c = 0; c < 16; ++c) acc[c] = __ldg(b + c);
#pragma unroll
    for (int kb = 0; kb < 27; kb += 9) {
        int idx[9];
#pragma unroll
        for (int t = 0; t < 9; ++t) idx[t] = __ldg(gi + (size_t)(kb + t) * n + j);
        float xv[9];
#pragma unroll
        for (int t = 0; t < 9; ++t) xv[t] = (idx[t] >= 0) ? __ldg(x + idx[t]) : 0.f;
#pragma unroll
        for (int t = 0; t < 9; ++t) {
#pragma unroll
            for (int c = 0; c < 16; ++c) acc[c] += xv[t] * Ws[(kb + t) * 16 + c];
        }
    }
    float4* o4 = (float4*)(out + (size_t)j * 16);
    float4* c4 = (float4*)(cache + (size_t)j * 16);
#pragma unroll
    for (int r = 0; r < 4; ++r) {
        float4 v = make_float4(fmaxf(acc[4*r], 0.f), fmaxf(acc[4*r+1], 0.f),
                               fmaxf(acc[4*r+2], 0.f), fmaxf(acc[4*r+3], 0.f));
        o4[r] = v; c4[r] = v;
    }
}

// ====== conv 16->16 (K=27): two output rows per thread ==================
__global__ __launch_bounds__(256, 3) void conv16_16j2(const float* __restrict__ x,
        const float* __restrict__ W, const int* __restrict__ gi,
        const float* __restrict__ b, float* __restrict__ out, int n) {
    __shared__ float4 Ws4[27 * 64];          // 27 KB
    const float4* Wg = (const float4*)W;
    for (int t = threadIdx.x; t < 27 * 64; t += 256) Ws4[t] = Wg[t];
    __syncthreads();
    const ulonglong2* Wu = (const ulonglong2*)Ws4;
    const int tid = threadIdx.x;
    const int j0 = blockIdx.x * 512 + tid;
    const int j1 = j0 + 256;
    const bool jv0 = j0 < n, jv1 = j1 < n;

    u64 acc[16];                              // [0..7] row j0, [8..15] row j1
    {
        const float4* b4 = (const float4*)b;
#pragma unroll
        for (int r = 0; r < 4; ++r) {
            float4 bb = __ldg(b4 + r);
            u64 lo = packf2(bb.x, bb.y), hi = packf2(bb.z, bb.w);
            acc[2*r] = lo; acc[2*r+1] = hi;
            acc[8 + 2*r] = lo; acc[8 + 2*r+1] = hi;
        }
    }
    int a0 = jv0 ? __ldg(gi + j0) : -1;
    int a1 = jv1 ? __ldg(gi + j1) : -1;
    for (int k = 0; k < 27; ++k) {
        const int i0 = a0, i1 = a1;
        a0 = (k < 26 && jv0) ? __ldg(gi + (size_t)(k + 1) * n + j0) : -1;
        a1 = (k < 26 && jv1) ? __ldg(gi + (size_t)(k + 1) * n + j1) : -1;
        if (!__ballot_sync(0xffffffffu, (i0 >= 0) || (i1 >= 0))) continue;
        const float4* xr0 = (const float4*)(x + (size_t)(i0 < 0 ? 0 : i0) * 16);
        const float4* xr1 = (const float4*)(x + (size_t)(i1 < 0 ? 0 : i1) * 16);
        float4 X0[4], X1[4];
#pragma unroll
        for (int q = 0; q < 4; ++q) {
            X0[q] = (i0 >= 0) ? __ldg(xr0 + q) : make_float4(0.f, 0.f, 0.f, 0.f);
            X1[q] = (i1 >= 0) ? __ldg(xr1 + q) : make_float4(0.f, 0.f, 0.f, 0.f);
        }
        const ulonglong2* Wk = Wu + (size_t)k * 64;
#pragma unroll
        for (int q = 0; q < 4; ++q) {
            float xs0[4] = {X0[q].x, X0[q].y, X0[q].z, X0[q].w};
            float xs1[4] = {X1[q].x, X1[q].y, X1[q].z, X1[q].w};
#pragma unroll
            for (int s = 0; s < 4; ++s) {
                int cc = q * 4 + s;
                u64 xx0 = bcast2(xs0[s]);
                u64 xx1 = bcast2(xs1[s]);
#pragma unroll
                for (int r = 0; r < 4; ++r) {
                    ulonglong2 wp = Wk[cc * 4 + r];
                    ffma2(acc[2*r],         xx0, wp.x);
                    ffma2(acc[2*r + 1],     xx0, wp.y);
                    ffma2(acc[8 + 2*r],     xx1, wp.x);
                    ffma2(acc[8 + 2*r + 1], xx1, wp.y);
                }
            }
        }
    }
#pragma unroll
    for (int o = 0; o < 2; ++o) {
        const int j = o ? j1 : j0;
        if (j >= n) continue;
        const u64* a = acc + o * 8;
        float4* o4 = (float4*)(out + (size_t)j * 16);
#pragma unroll
        for (int r = 0; r < 4; ++r) {
            F2U a0u, a1u; a0u.u = a[2*r]; a1u.u = a[2*r+1];
            o4[r] = make_float4(fmaxf(a0u.f.x, 0.f), fmaxf(a0u.f.y, 0.f),
                                fmaxf(a1u.f.x, 0.f), fmaxf(a1u.f.y, 0.f));
        }
    }
}

// ====== conv 16->32 (K=8, downsample): two output rows per thread =======
__global__ __launch_bounds__(256, 2) void conv16_32j2(const float* __restrict__ x,
        const float* __restrict__ W, const int* __restrict__ gi,
        const float* __restrict__ b, float* __restrict__ out, int n) {
    __shared__ float4 Ws4[8 * 128];          // 16 KB
    const float4* Wg = (const float4*)W;
    for (int t = threadIdx.x; t < 8 * 128; t += 256) Ws4[t] = Wg[t];
    __syncthreads();
    const ulonglong2* Wu = (const ulonglong2*)Ws4;
    const int tid = threadIdx.x;
    const int j0 = blockIdx.x * 512 + tid;
    const int j1 = j0 + 256;
    const bool jv0 = j0 < n, jv1 = j1 < n;

    u64 acc[32];                              // [0..15] row j0, [16..31] row j1
    {
        const float4* b4 = (const float4*)b;
#pragma unroll
        for (int r = 0; r < 8; ++r) {
            float4 bb = __ldg(b4 + r);
            u64 lo = packf2(bb.x, bb.y), hi = packf2(bb.z, bb.w);
            acc[2*r] = lo; acc[2*r+1] = hi;
            acc[16 + 2*r] = lo; acc[16 + 2*r+1] = hi;
        }
    }
    int a0 = jv0 ? __ldg(gi + j0) : -1;
    int a1 = jv1 ? __ldg(gi + j1) : -1;
    for (int k = 0; k < 8; ++k) {
        const int i0 = a0, i1 = a1;
        a0 = (k < 7 && jv0) ? __ldg(gi + (size_t)(k + 1) * n + j0) : -1;
        a1 = (k < 7 && jv1) ? __ldg(gi + (size_t)(k + 1) * n + j1) : -1;
        if (!__ballot_sync(0xffffffffu, (i0 >= 0) || (i1 >= 0))) continue;
        const float4* xr0 = (const float4*)(x + (size_t)(i0 < 0 ? 0 : i0) * 16);
        const float4* xr1 = (const float4*)(x + (size_t)(i1 < 0 ? 0 : i1) * 16);
        float4 X0[4], X1[4];
#pragma unroll
        for (int q = 0; q < 4; ++q) {
            X0[q] = (i0 >= 0) ? __ldg(xr0 + q) : make_float4(0.f, 0.f, 0.f, 0.f);
            X1[q] = (i1 >= 0) ? __ldg(xr1 + q) : make_float4(0.f, 0.f, 0.f, 0.f);
        }
        const ulonglong2* Wk = Wu + (size_t)k * 128;
#pragma unroll
        for (int q = 0; q < 4; ++q) {
            float xs0[4] = {X0[q].x, X0[q].y, X0[q].z, X0[q].w};
            float xs1[4] = {X1[q].x, X1[q].y, X1[q].z, X1[q].w};
#pragma unroll
            for (int s = 0; s < 4; ++s) {
                int cc = q * 4 + s;
                u64 xx0 = bcast2(xs0[s]);
                u64 xx1 = bcast2(xs1[s]);
#pragma unroll
                for (int r = 0; r < 8; ++r) {
                    ulonglong2 wp = Wk[cc * 8 + r];
                    ffma2(acc[2*r],          xx0, wp.x);
                    ffma2(acc[2*r + 1],      xx0, wp.y);
                    ffma2(acc[16 + 2*r],     xx1, wp.x);
                    ffma2(acc[16 + 2*r + 1], xx1, wp.y);
                }
            }
        }
    }
#pragma unroll
    for (int o = 0; o < 2; ++o) {
        const int j = o ? j1 : j0;
        if (j >= n) continue;
        const u64* a = acc + o * 16;
        float4* o4 = (float4*)(out + (size_t)j * 32);
#pragma unroll
        for (int r = 0; r < 8; ++r) {
            F2U a0u, a1u; a0u.u = a[2*r]; a1u.u = a[2*r+1];
            o4[r] = make_float4(fmaxf(a0u.f.x, 0.f), fmaxf(a0u.f.y, 0.f),
                                fmaxf(a1u.f.x, 0.f), fmaxf(a1u.f.y, 0.f));
        }
    }
}

// ====== conv 32->32 (K=27): two output rows per thread (R11 winner) =====
template <int EPI>   // 0 = bias+relu, 1 = bias+residual, 2 = bias only
__global__ __launch_bounds__(256) void conv32_32j2(const float* __restrict__ x,
        const float* __restrict__ W, const int* __restrict__ gi,
        const float* __restrict__ b, const float* __restrict__ skip,
        float* __restrict__ out, int n) {
    extern __shared__ float4 Ws4[];          // 27 * 256 float4 = 108 KB
    const float4* Wg = (const float4*)W;
    for (int t = threadIdx.x; t < 27 * 256; t += 256) Ws4[t] = Wg[t];
    __syncthreads();
    const ulonglong2* Wu = (const ulonglong2*)Ws4;
    const int tid = threadIdx.x;
    const int j0 = blockIdx.x * 512 + tid;
    const int j1 = j0 + 256;
    const bool jv0 = j0 < n, jv1 = j1 < n;

    u64 acc[32];                              // [0..15] row j0, [16..31] row j1
    {
        const float4* b4 = (const float4*)b;
#pragma unroll
        for (int r = 0; r < 8; ++r) {
            float4 bb = __ldg(b4 + r);
            u64 lo = packf2(bb.x, bb.y), hi = packf2(bb.z, bb.w);
            acc[2*r] = lo; acc[2*r+1] = hi;
            acc[16 + 2*r] = lo; acc[16 + 2*r+1] = hi;
        }
    }
    int a0 = jv0 ? __ldg(gi + j0) : -1;
    int a1 = jv1 ? __ldg(gi + j1) : -1;
    for (int k = 0; k < 27; ++k) {
        const int i0 = a0, i1 = a1;
        a0 = (k < 26 && jv0) ? __ldg(gi + (size_t)(k + 1) * n + j0) : -1;
        a1 = (k < 26 && jv1) ? __ldg(gi + (size_t)(k + 1) * n + j1) : -1;
        if (!__ballot_sync(0xffffffffu, (i0 >= 0) || (i1 >= 0))) continue;
        const float4* xr0 = (const float4*)(x + (size_t)(i0 < 0 ? 0 : i0) * 32);
        const float4* xr1 = (const float4*)(x + (size_t)(i1 < 0 ? 0 : i1) * 32);
        const ulonglong2* Wk = Wu + (size_t)k * 256;
#pragma unroll
        for (int h = 0; h < 2; ++h) {         // input-channel halves keep regs low
            float4 X0[4], X1[4];
#pragma unroll
            for (int q = 0; q < 4; ++q) {
                X0[q] = (i0 >= 0) ? __ldg(xr0 + h * 4 + q) : make_float4(0.f, 0.f, 0.f, 0.f);
                X1[q] = (i1 >= 0) ? __ldg(xr1 + h * 4 + q) : make_float4(0.f, 0.f, 0.f, 0.f);
            }
#pragma unroll
            for (int q = 0; q < 4; ++q) {
                float xs0[4] = {X0[q].x, X0[q].y, X0[q].z, X0[q].w};
                float xs1[4] = {X1[q].x, X1[q].y, X1[q].z, X1[q].w};
#pragma unroll
                for (int s = 0; s < 4; ++s) {
                    int cc = h * 16 + q * 4 + s;
                    u64 xx0 = bcast2(xs0[s]);
                    u64 xx1 = bcast2(xs1[s]);
#pragma unroll
                    for (int r = 0; r < 8; ++r) {
                        ulonglong2 wp = Wk[cc * 8 + r];
                        ffma2(acc[2*r],          xx0, wp.x);
                        ffma2(acc[2*r + 1],      xx0, wp.y);
                        ffma2(acc[16 + 2*r],     xx1, wp.x);
                        ffma2(acc[16 + 2*r + 1], xx1, wp.y);
                    }
                }
            }
        }
    }
#pragma unroll
    for (int o = 0; o < 2; ++o) {
        const int j = o ? j1 : j0;
        if (j >= n) continue;
        const u64* a = acc + o * 16;
        float4* o4 = (float4*)(out + (size_t)j * 32);
        const float4* s4 = (EPI == 1) ? (const float4*)(skip + (size_t)j * 32) : nullptr;
#pragma unroll
        for (int r = 0; r < 8; ++r) {
            F2U a0u, a1u; a0u.u = a[2*r]; a1u.u = a[2*r+1];
            float4 v = make_float4(a0u.f.x, a0u.f.y, a1u.f.x, a1u.f.y);
            if (EPI == 0) {
                v.x = fmaxf(v.x, 0.f); v.y = fmaxf(v.y, 0.f);
                v.z = fmaxf(v.z, 0.f); v.w = fmaxf(v.w, 0.f);
            }
            if (EPI == 1) {
                float4 sv = __ldg(s4 + r);
                v.x += sv.x; v.y += sv.y; v.z += sv.z; v.w += sv.w;
            }
            o4[r] = v;
        }
    }
}

// ---------------- host orchestration ----------------
extern "C" void kernel_launch(void* const* d_in, const int* in_sizes, int n_in,
                              void* d_out, int out_size) {
    const float* in_feats = (const float*)d_in[0];
    const float* W_first  = (const float*)d_in[1];
    const float* b_first  = (const float*)d_in[2];
    const float* W_pre    = (const float*)d_in[3];
    const float* b_pre    = (const float*)d_in[4];
    const float* W_down   = (const float*)d_in[5];
    const float* b_down   = (const float*)d_in[6];
    const float* W_r0     = (const float*)d_in[7];
    const float* b_r0     = (const float*)d_in[8];
    const float* W_r1     = (const float*)d_in[9];
    const float* b_r1     = (const float*)d_in[10];
    const float* W_fin    = (const float*)d_in[11];
    const float* b_fin    = (const float*)d_in[12];
    const int* km0_in  = (const int*)d_in[13];
    const int* km0_out = (const int*)d_in[14];
    const int* kmd_in  = (const int*)d_in[15];
    const int* kmd_out = (const int*)d_in[16];
    const int* km1_in  = (const int*)d_in[17];
    const int* km1_out = (const int*)d_in[18];

    const int n0 = in_sizes[0];
    const int P0 = in_sizes[13] / 27;
    const int Pd = in_sizes[15] / 8;
    const int P1 = in_sizes[17] / 27;
    const int n1 = (out_size - n0 * 16) / 32;

    float* out_fin    = (float*)d_out;
    float* out_cached = (float*)d_out + (size_t)n1 * 32;

    float *x0, *x1, *x2, *r0, *r1;
    int *gi0, *gid, *gi1;
    cudaGetSymbolAddress((void**)&x0, g_x0);
    cudaGetSymbolAddress((void**)&x1, g_x1);
    cudaGetSymbolAddress((void**)&x2, g_x2);
    cudaGetSymbolAddress((void**)&r0, g_r0);
    cudaGetSymbolAddress((void**)&r1, g_r1);
    cudaGetSymbolAddress((void**)&gi0, g_gi0);
    cudaGetSymbolAddress((void**)&gid, g_gid);
    cudaGetSymbolAddress((void**)&gi1, g_gi1);

    const int SMEM32 = 27 * 256 * sizeof(float4);  // 110592 B
    static bool attr_done = false;
    if (!attr_done) {
        cudaFuncSetAttribute(conv32_32j2<0>, cudaFuncAttributeMaxDynamicSharedMemorySize, SMEM32);
        cudaFuncSetAttribute(conv32_32j2<1>, cudaFuncAttributeMaxDynamicSharedMemorySize, SMEM32);
        cudaFuncSetAttribute(conv32_32j2<2>, cudaFuncAttributeMaxDynamicSharedMemorySize, SMEM32);
        attr_done = true;
    }

    auto ceil_div = [](int a, int b) { return (a + b - 1) / b; };
    const int T = 256;

    // ---- build inverse maps ----
    cudaMemsetAsync(gi0, 0xFF, (size_t)27 * n0 * sizeof(int), 0);
    cudaMemsetAsync(gid, 0xFF, (size_t)8 * n1 * sizeof(int), 0);
    cudaMemsetAsync(gi1, 0xFF, (size_t)27 * n1 * sizeof(int), 0);
    {
        dim3 g0(ceil_div(P0, T), 27);
        build_gi<<<g0, T>>>(km0_in, km0_out, gi0, P0, n0);
        dim3 gd(ceil_div(Pd, T), 8);
        build_gi<<<gd, T>>>(kmd_in, kmd_out, gid, Pd, n1);
        dim3 g1(ceil_div(P1, T), 27);
        build_gi<<<g1, T>>>(km1_in, km1_out, gi1, P1, n1);
    }

    conv1_16<<<ceil_div(n0, T), T>>>(in_feats, W_first, gi0, b_first, x0, out_cached, n0);
    conv16_16j2<<<ceil_div(n0, 512), T>>>(x0, W_pre, gi0, b_pre, x1, n0);
    conv16_32j2<<<ceil_div(n1, 512), T>>>(x1, W_down, gid, b_down, x2, n1);

    const int gb = ceil_div(n1, 512);
    conv32_32j2<0><<<gb, 256, SMEM32>>>(x2, W_r0, gi1, b_r0, nullptr, r0, n1);
    conv32_32j2<1><<<gb, 256, SMEM32>>>(r0, W_r1, gi1, b_r1, x2, r1, n1);
    conv32_32j2<2><<<gb, 256, SMEM32>>>(r1, W_fin, gi1, b_fin, nullptr, out_fin, n1);
}

// round 13
// speedup vs baseline: 29.0229x; 1.0279x over previous
#include <cuda_runtime.h>
#include <cstdint>

// ---------------- static scratch (no allocations allowed) ----------------
#define MAXN0 600000
__device__ float g_x0[MAXN0 * 16];
__device__ float g_x1[MAXN0 * 16];
__device__ float g_x2[MAXN0 * 32];
__device__ float g_r0[MAXN0 * 32];
__device__ float g_r1[MAXN0 * 32];
__device__ int   g_gi0[27 * MAXN0];
__device__ int   g_gid[8 * MAXN0];
__device__ int   g_gi1[27 * MAXN0];

typedef unsigned long long u64;
union F2U { u64 u; float2 f; };

__device__ __forceinline__ u64 bcast2(float s) {
    u64 r; asm("mov.b64 %0, {%1, %1};" : "=l"(r) : "r"(__float_as_uint(s))); return r;
}
__device__ __forceinline__ void ffma2(u64& a, u64 x, u64 w) {
    asm("fma.rn.f32x2 %0, %1, %2, %3;" : "=l"(a) : "l"(x), "l"(w), "l"(a));
}
__device__ __forceinline__ u64 packf2(float lo, float hi) {
    u64 r; asm("mov.b64 %0, {%1, %2};" : "=l"(r) : "r"(__float_as_uint(lo)), "r"(__float_as_uint(hi))); return r;
}

// ---------------- inverse-map build ----------------
__global__ void build_gi(const int* __restrict__ kin, const int* __restrict__ kout,
                         int* __restrict__ gi, int P, int n) {
    const int k = blockIdx.y;
    int p = blockIdx.x * blockDim.x + threadIdx.x;
    if (p >= P) return;
    const size_t base = (size_t)k * P;
    int j = kout[base + p];
    if (j < n) gi[(size_t)k * n + j] = kin[base + p];
}

// ---------------- conv 1->16: two output rows per thread ----------------
__global__ __launch_bounds__(256) void conv1_16j2(const float* __restrict__ x,
        const float* __restrict__ W, const int* __restrict__ gi,
        const float* __restrict__ b, float* __restrict__ out,
        float* __restrict__ cache, int n) {
    __shared__ float Ws[27 * 16];
    for (int t = threadIdx.x; t < 27 * 16; t += 256) Ws[t] = W[t];
    __syncthreads();
    const int tid = threadIdx.x;
    const int j0 = blockIdx.x * 512 + tid;
    const int j1 = j0 + 256;
    const bool jv0 = j0 < n, jv1 = j1 < n;
    if (!jv0) return;
    float acc0[16], acc1[16];
#pragma unroll
    for (int c = 0; c < 16; ++c) { float bb = __ldg(b + c); acc0[c] = bb; acc1[c] = bb; }
#pragma unroll
    for (int kb = 0; kb < 27; kb += 9) {
        int id0[9], id1[9];
#pragma unroll
        for (int t = 0; t < 9; ++t) {
            id0[t] = __ldg(gi + (size_t)(kb + t) * n + j0);
            id1[t] = jv1 ? __ldg(gi + (size_t)(kb + t) * n + j1) : -1;
        }
        float xv0[9], xv1[9];
#pragma unroll
        for (int t = 0; t < 9; ++t) {
            xv0[t] = (id0[t] >= 0) ? __ldg(x + id0[t]) : 0.f;
            xv1[t] = (id1[t] >= 0) ? __ldg(x + id1[t]) : 0.f;
        }
#pragma unroll
        for (int t = 0; t < 9; ++t) {
#pragma unroll
            for (int c = 0; c < 16; ++c) {
                acc0[c] += xv0[t] * Ws[(kb + t) * 16 + c];
                acc1[c] += xv1[t] * Ws[(kb + t) * 16 + c];
            }
        }
    }
    {
        float4* o4 = (float4*)(out + (size_t)j0 * 16);
        float4* c4 = (float4*)(cache + (size_t)j0 * 16);
#pragma unroll
        for (int r = 0; r < 4; ++r) {
            float4 v = make_float4(fmaxf(acc0[4*r], 0.f), fmaxf(acc0[4*r+1], 0.f),
                                   fmaxf(acc0[4*r+2], 0.f), fmaxf(acc0[4*r+3], 0.f));
            o4[r] = v; c4[r] = v;
        }
    }
    if (jv1) {
        float4* o4 = (float4*)(out + (size_t)j1 * 16);
        float4* c4 = (float4*)(cache + (size_t)j1 * 16);
#pragma unroll
        for (int r = 0; r < 4; ++r) {
            float4 v = make_float4(fmaxf(acc1[4*r], 0.f), fmaxf(acc1[4*r+1], 0.f),
                                   fmaxf(acc1[4*r+2], 0.f), fmaxf(acc1[4*r+3], 0.f));
            o4[r] = v; c4[r] = v;
        }
    }
}

// ====== conv 16->16 (K=27): two output rows per thread (R12) ============
__global__ __launch_bounds__(256, 3) void conv16_16j2(const float* __restrict__ x,
        const float* __restrict__ W, const int* __restrict__ gi,
        const float* __restrict__ b, float* __restrict__ out, int n) {
    __shared__ float4 Ws4[27 * 64];          // 27 KB
    const float4* Wg = (const float4*)W;
    for (int t = threadIdx.x; t < 27 * 64; t += 256) Ws4[t] = Wg[t];
    __syncthreads();
    const ulonglong2* Wu = (const ulonglong2*)Ws4;
    const int tid = threadIdx.x;
    const int j0 = blockIdx.x * 512 + tid;
    const int j1 = j0 + 256;
    const bool jv0 = j0 < n, jv1 = j1 < n;

    u64 acc[16];                              // [0..7] row j0, [8..15] row j1
    {
        const float4* b4 = (const float4*)b;
#pragma unroll
        for (int r = 0; r < 4; ++r) {
            float4 bb = __ldg(b4 + r);
            u64 lo = packf2(bb.x, bb.y), hi = packf2(bb.z, bb.w);
            acc[2*r] = lo; acc[2*r+1] = hi;
            acc[8 + 2*r] = lo; acc[8 + 2*r+1] = hi;
        }
    }
    int a0 = jv0 ? __ldg(gi + j0) : -1;
    int a1 = jv1 ? __ldg(gi + j1) : -1;
    for (int k = 0; k < 27; ++k) {
        const int i0 = a0, i1 = a1;
        a0 = (k < 26 && jv0) ? __ldg(gi + (size_t)(k + 1) * n + j0) : -1;
        a1 = (k < 26 && jv1) ? __ldg(gi + (size_t)(k + 1) * n + j1) : -1;
        if (!__ballot_sync(0xffffffffu, (i0 >= 0) || (i1 >= 0))) continue;
        const float4* xr0 = (const float4*)(x + (size_t)(i0 < 0 ? 0 : i0) * 16);
        const float4* xr1 = (const float4*)(x + (size_t)(i1 < 0 ? 0 : i1) * 16);
        float4 X0[4], X1[4];
#pragma unroll
        for (int q = 0; q < 4; ++q) {
            X0[q] = (i0 >= 0) ? __ldg(xr0 + q) : make_float4(0.f, 0.f, 0.f, 0.f);
            X1[q] = (i1 >= 0) ? __ldg(xr1 + q) : make_float4(0.f, 0.f, 0.f, 0.f);
        }
        const ulonglong2* Wk = Wu + (size_t)k * 64;
#pragma unroll
        for (int q = 0; q < 4; ++q) {
            float xs0[4] = {X0[q].x, X0[q].y, X0[q].z, X0[q].w};
            float xs1[4] = {X1[q].x, X1[q].y, X1[q].z, X1[q].w};
#pragma unroll
            for (int s = 0; s < 4; ++s) {
                int cc = q * 4 + s;
                u64 xx0 = bcast2(xs0[s]);
                u64 xx1 = bcast2(xs1[s]);
#pragma unroll
                for (int r = 0; r < 4; ++r) {
                    ulonglong2 wp = Wk[cc * 4 + r];
                    ffma2(acc[2*r],         xx0, wp.x);
                    ffma2(acc[2*r + 1],     xx0, wp.y);
                    ffma2(acc[8 + 2*r],     xx1, wp.x);
                    ffma2(acc[8 + 2*r + 1], xx1, wp.y);
                }
            }
        }
    }
#pragma unroll
    for (int o = 0; o < 2; ++o) {
        const int j = o ? j1 : j0;
        if (j >= n) continue;
        const u64* a = acc + o * 8;
        float4* o4 = (float4*)(out + (size_t)j * 16);
#pragma unroll
        for (int r = 0; r < 4; ++r) {
            F2U a0u, a1u; a0u.u = a[2*r]; a1u.u = a[2*r+1];
            o4[r] = make_float4(fmaxf(a0u.f.x, 0.f), fmaxf(a0u.f.y, 0.f),
                                fmaxf(a1u.f.x, 0.f), fmaxf(a1u.f.y, 0.f));
        }
    }
}

// ====== conv 16->32 (K=8, downsample): two output rows per thread (R12) =
__global__ __launch_bounds__(256, 2) void conv16_32j2(const float* __restrict__ x,
        const float* __restrict__ W, const int* __restrict__ gi,
        const float* __restrict__ b, float* __restrict__ out, int n) {
    __shared__ float4 Ws4[8 * 128];          // 16 KB
    const float4* Wg = (const float4*)W;
    for (int t = threadIdx.x; t < 8 * 128; t += 256) Ws4[t] = Wg[t];
    __syncthreads();
    const ulonglong2* Wu = (const ulonglong2*)Ws4;
    const int tid = threadIdx.x;
    const int j0 = blockIdx.x * 512 + tid;
    const int j1 = j0 + 256;
    const bool jv0 = j0 < n, jv1 = j1 < n;

    u64 acc[32];
    {
        const float4* b4 = (const float4*)b;
#pragma unroll
        for (int r = 0; r < 8; ++r) {
            float4 bb = __ldg(b4 + r);
            u64 lo = packf2(bb.x, bb.y), hi = packf2(bb.z, bb.w);
            acc[2*r] = lo; acc[2*r+1] = hi;
            acc[16 + 2*r] = lo; acc[16 + 2*r+1] = hi;
        }
    }
    int a0 = jv0 ? __ldg(gi + j0) : -1;
    int a1 = jv1 ? __ldg(gi + j1) : -1;
    for (int k = 0; k < 8; ++k) {
        const int i0 = a0, i1 = a1;
        a0 = (k < 7 && jv0) ? __ldg(gi + (size_t)(k + 1) * n + j0) : -1;
        a1 = (k < 7 && jv1) ? __ldg(gi + (size_t)(k + 1) * n + j1) : -1;
        if (!__ballot_sync(0xffffffffu, (i0 >= 0) || (i1 >= 0))) continue;
        const float4* xr0 = (const float4*)(x + (size_t)(i0 < 0 ? 0 : i0) * 16);
        const float4* xr1 = (const float4*)(x + (size_t)(i1 < 0 ? 0 : i1) * 16);
        float4 X0[4], X1[4];
#pragma unroll
        for (int q = 0; q < 4; ++q) {
            X0[q] = (i0 >= 0) ? __ldg(xr0 + q) : make_float4(0.f, 0.f, 0.f, 0.f);
            X1[q] = (i1 >= 0) ? __ldg(xr1 + q) : make_float4(0.f, 0.f, 0.f, 0.f);
        }
        const ulonglong2* Wk = Wu + (size_t)k * 128;
#pragma unroll
        for (int q = 0; q < 4; ++q) {
            float xs0[4] = {X0[q].x, X0[q].y, X0[q].z, X0[q].w};
            float xs1[4] = {X1[q].x, X1[q].y, X1[q].z, X1[q].w};
#pragma unroll
            for (int s = 0; s < 4; ++s) {
                int cc = q * 4 + s;
                u64 xx0 = bcast2(xs0[s]);
                u64 xx1 = bcast2(xs1[s]);
#pragma unroll
                for (int r = 0; r < 8; ++r) {
                    ulonglong2 wp = Wk[cc * 8 + r];
                    ffma2(acc[2*r],          xx0, wp.x);
                    ffma2(acc[2*r + 1],      xx0, wp.y);
                    ffma2(acc[16 + 2*r],     xx1, wp.x);
                    ffma2(acc[16 + 2*r + 1], xx1, wp.y);
                }
            }
        }
    }
#pragma unroll
    for (int o = 0; o < 2; ++o) {
        const int j = o ? j1 : j0;
        if (j >= n) continue;
        const u64* a = acc + o * 16;
        float4* o4 = (float4*)(out + (size_t)j * 32);
#pragma unroll
        for (int r = 0; r < 8; ++r) {
            F2U a0u, a1u; a0u.u = a[2*r]; a1u.u = a[2*r+1];
            o4[r] = make_float4(fmaxf(a0u.f.x, 0.f), fmaxf(a0u.f.y, 0.f),
                                fmaxf(a1u.f.x, 0.f), fmaxf(a1u.f.y, 0.f));
        }
    }
}

// ====== conv 32->32 (K=27): two rows/thread, 2 CTAs/SM forced ===========
template <int EPI>   // 0 = bias+relu, 1 = bias+residual, 2 = bias only
__global__ __launch_bounds__(256, 2) void conv32_32j2(const float* __restrict__ x,
        const float* __restrict__ W, const int* __restrict__ gi,
        const float* __restrict__ b, const float* __restrict__ skip,
        float* __restrict__ out, int n) {
    extern __shared__ float4 Ws4[];          // 27 * 256 float4 = 108 KB
    const float4* Wg = (const float4*)W;
    for (int t = threadIdx.x; t < 27 * 256; t += 256) Ws4[t] = Wg[t];
    __syncthreads();
    const ulonglong2* Wu = (const ulonglong2*)Ws4;
    const int tid = threadIdx.x;
    const int j0 = blockIdx.x * 512 + tid;
    const int j1 = j0 + 256;
    const bool jv0 = j0 < n, jv1 = j1 < n;

    u64 acc[32];                              // [0..15] row j0, [16..31] row j1
    {
        const float4* b4 = (const float4*)b;
#pragma unroll
        for (int r = 0; r < 8; ++r) {
            float4 bb = __ldg(b4 + r);
            u64 lo = packf2(bb.x, bb.y), hi = packf2(bb.z, bb.w);
            acc[2*r] = lo; acc[2*r+1] = hi;
            acc[16 + 2*r] = lo; acc[16 + 2*r+1] = hi;
        }
    }
    int a0 = jv0 ? __ldg(gi + j0) : -1;
    int a1 = jv1 ? __ldg(gi + j1) : -1;
    for (int k = 0; k < 27; ++k) {
        const int i0 = a0, i1 = a1;
        a0 = (k < 26 && jv0) ? __ldg(gi + (size_t)(k + 1) * n + j0) : -1;
        a1 = (k < 26 && jv1) ? __ldg(gi + (size_t)(k + 1) * n + j1) : -1;
        if (!__ballot_sync(0xffffffffu, (i0 >= 0) || (i1 >= 0))) continue;
        const float4* xr0 = (const float4*)(x + (size_t)(i0 < 0 ? 0 : i0) * 32);
        const float4* xr1 = (const float4*)(x + (size_t)(i1 < 0 ? 0 : i1) * 32);
        const ulonglong2* Wk = Wu + (size_t)k * 256;
#pragma unroll
        for (int h = 0; h < 2; ++h) {         // input-channel halves keep regs low
            float4 X0[4], X1[4];
#pragma unroll
            for (int q = 0; q < 4; ++q) {
                X0[q] = (i0 >= 0) ? __ldg(xr0 + h * 4 + q) : make_float4(0.f, 0.f, 0.f, 0.f);
                X1[q] = (i1 >= 0) ? __ldg(xr1 + h * 4 + q) : make_float4(0.f, 0.f, 0.f, 0.f);
            }
#pragma unroll
            for (int q = 0; q < 4; ++q) {
                float xs0[4] = {X0[q].x, X0[q].y, X0[q].z, X0[q].w};
                float xs1[4] = {X1[q].x, X1[q].y, X1[q].z, X1[q].w};
#pragma unroll
                for (int s = 0; s < 4; ++s) {
                    int cc = h * 16 + q * 4 + s;
                    u64 xx0 = bcast2(xs0[s]);
                    u64 xx1 = bcast2(xs1[s]);
#pragma unroll
                    for (int r = 0; r < 8; ++r) {
                        ulonglong2 wp = Wk[cc * 8 + r];
                        ffma2(acc[2*r],          xx0, wp.x);
                        ffma2(acc[2*r + 1],      xx0, wp.y);
                        ffma2(acc[16 + 2*r],     xx1, wp.x);
                        ffma2(acc[16 + 2*r + 1], xx1, wp.y);
                    }
                }
            }
        }
    }
#pragma unroll
    for (int o = 0; o < 2; ++o) {
        const int j = o ? j1 : j0;
        if (j >= n) continue;
        const u64* a = acc + o * 16;
        float4* o4 = (float4*)(out + (size_t)j * 32);
        const float4* s4 = (EPI == 1) ? (const float4*)(skip + (size_t)j * 32) : nullptr;
#pragma unroll
        for (int r = 0; r < 8; ++r) {
            F2U a0u, a1u; a0u.u = a[2*r]; a1u.u = a[2*r+1];
            float4 v = make_float4(a0u.f.x, a0u.f.y, a1u.f.x, a1u.f.y);
            if (EPI == 0) {
                v.x = fmaxf(v.x, 0.f); v.y = fmaxf(v.y, 0.f);
                v.z = fmaxf(v.z, 0.f); v.w = fmaxf(v.w, 0.f);
            }
            if (EPI == 1) {
                float4 sv = __ldg(s4 + r);
                v.x += sv.x; v.y += sv.y; v.z += sv.z; v.w += sv.w;
            }
            o4[r] = v;
        }
    }
}

// ---------------- host orchestration ----------------
extern "C" void kernel_launch(void* const* d_in, const int* in_sizes, int n_in,
                              void* d_out, int out_size) {
    const float* in_feats = (const float*)d_in[0];
    const float* W_first  = (const float*)d_in[1];
    const float* b_first  = (const float*)d_in[2];
    const float* W_pre    = (const float*)d_in[3];
    const float* b_pre    = (const float*)d_in[4];
    const float* W_down   = (const float*)d_in[5];
    const float* b_down   = (const float*)d_in[6];
    const float* W_r0     = (const float*)d_in[7];
    const float* b_r0     = (const float*)d_in[8];
    const float* W_r1     = (const float*)d_in[9];
    const float* b_r1     = (const float*)d_in[10];
    const float* W_fin    = (const float*)d_in[11];
    const float* b_fin    = (const float*)d_in[12];
    const int* km0_in  = (const int*)d_in[13];
    const int* km0_out = (const int*)d_in[14];
    const int* kmd_in  = (const int*)d_in[15];
    const int* kmd_out = (const int*)d_in[16];
    const int* km1_in  = (const int*)d_in[17];
    const int* km1_out = (const int*)d_in[18];

    const int n0 = in_sizes[0];
    const int P0 = in_sizes[13] / 27;
    const int Pd = in_sizes[15] / 8;
    const int P1 = in_sizes[17] / 27;
    const int n1 = (out_size - n0 * 16) / 32;

    float* out_fin    = (float*)d_out;
    float* out_cached = (float*)d_out + (size_t)n1 * 32;

    float *x0, *x1, *x2, *r0, *r1;
    int *gi0, *gid, *gi1;
    cudaGetSymbolAddress((void**)&x0, g_x0);
    cudaGetSymbolAddress((void**)&x1, g_x1);
    cudaGetSymbolAddress((void**)&x2, g_x2);
    cudaGetSymbolAddress((void**)&r0, g_r0);
    cudaGetSymbolAddress((void**)&r1, g_r1);
    cudaGetSymbolAddress((void**)&gi0, g_gi0);
    cudaGetSymbolAddress((void**)&gid, g_gid);
    cudaGetSymbolAddress((void**)&gi1, g_gi1);

    const int SMEM32 = 27 * 256 * sizeof(float4);  // 110592 B
    static bool attr_done = false;
    if (!attr_done) {
        cudaFuncSetAttribute(conv32_32j2<0>, cudaFuncAttributeMaxDynamicSharedMemorySize, SMEM32);
        cudaFuncSetAttribute(conv32_32j2<1>, cudaFuncAttributeMaxDynamicSharedMemorySize, SMEM32);
        cudaFuncSetAttribute(conv32_32j2<2>, cudaFuncAttributeMaxDynamicSharedMemorySize, SMEM32);
        attr_done = true;
    }

    auto ceil_div = [](int a, int b) { return (a + b - 1) / b; };
    const int T = 256;

    // ---- build inverse maps ----
    cudaMemsetAsync(gi0, 0xFF, (size_t)27 * n0 * sizeof(int), 0);
    cudaMemsetAsync(gid, 0xFF, (size_t)8 * n1 * sizeof(int), 0);
    cudaMemsetAsync(gi1, 0xFF, (size_t)27 * n1 * sizeof(int), 0);
    {
        dim3 g0(ceil_div(P0, T), 27);
        build_gi<<<g0, T>>>(km0_in, km0_out, gi0, P0, n0);
        dim3 gd(ceil_div(Pd, T), 8);
        build_gi<<<gd, T>>>(kmd_in, kmd_out, gid, Pd, n1);
        dim3 g1(ceil_div(P1, T), 27);
        build_gi<<<g1, T>>>(km1_in, km1_out, gi1, P1, n1);
    }

    conv1_16j2<<<ceil_div(n0, 512), T>>>(in_feats, W_first, gi0, b_first, x0, out_cached, n0);
    conv16_16j2<<<ceil_div(n0, 512), T>>>(x0, W_pre, gi0, b_pre, x1, n0);
    conv16_32j2<<<ceil_div(n1, 512), T>>>(x1, W_down, gid, b_down, x2, n1);

    const int gb = ceil_div(n1, 512);
    conv32_32j2<0><<<gb, 256, SMEM32>>>(x2, W_r0, gi1, b_r0, nullptr, r0, n1);
    conv32_32j2<1><<<gb, 256, SMEM32>>>(r0, W_r1, gi1, b_r1, x2, r1, n1);
    conv32_32j2<2><<<gb, 256, SMEM32>>>(r1, W_fin, gi1, b_fin, nullptr, out_fin, n1);
}

// round 14
// speedup vs baseline: 29.0437x; 1.0007x over previous
#include <cuda_runtime.h>
#include <cstdint>

// ---------------- static scratch (no allocations allowed) ----------------
#define MAXN0 600000
__device__ float g_x0[MAXN0 * 16];
__device__ float g_x1[MAXN0 * 16];
__device__ float g_x2[MAXN0 * 32];
__device__ float g_r0[MAXN0 * 32];
__device__ float g_r1[MAXN0 * 32];
__device__ int   g_gi0[27 * MAXN0];
__device__ int   g_gid[8 * MAXN0];
__device__ int   g_gi1[27 * MAXN0];

typedef unsigned long long u64;
union F2U { u64 u; float2 f; };

__device__ __forceinline__ u64 bcast2(float s) {
    u64 r; asm("mov.b64 %0, {%1, %1};" : "=l"(r) : "r"(__float_as_uint(s))); return r;
}
__device__ __forceinline__ void ffma2(u64& a, u64 x, u64 w) {
    asm("fma.rn.f32x2 %0, %1, %2, %3;" : "=l"(a) : "l"(x), "l"(w), "l"(a));
}
__device__ __forceinline__ u64 packf2(float lo, float hi) {
    u64 r; asm("mov.b64 %0, {%1, %2};" : "=l"(r) : "r"(__float_as_uint(lo)), "r"(__float_as_uint(hi))); return r;
}

// ---------------- inverse-map build ----------------
__global__ void build_gi(const int* __restrict__ kin, const int* __restrict__ kout,
                         int* __restrict__ gi, int P, int n) {
    const int k = blockIdx.y;
    int p = blockIdx.x * blockDim.x + threadIdx.x;
    if (p >= P) return;
    const size_t base = (size_t)k * P;
    int j = kout[base + p];
    if (j < n) gi[(size_t)k * n + j] = kin[base + p];
}

// ---------------- conv 1->16: two output rows per thread (R13) ----------
__global__ __launch_bounds__(256) void conv1_16j2(const float* __restrict__ x,
        const float* __restrict__ W, const int* __restrict__ gi,
        const float* __restrict__ b, float* __restrict__ out,
        float* __restrict__ cache, int n) {
    __shared__ float Ws[27 * 16];
    for (int t = threadIdx.x; t < 27 * 16; t += 256) Ws[t] = W[t];
    __syncthreads();
    const int tid = threadIdx.x;
    const int j0 = blockIdx.x * 512 + tid;
    const int j1 = j0 + 256;
    const bool jv1 = j1 < n;
    if (j0 >= n) return;
    float acc0[16], acc1[16];
#pragma unroll
    for (int c = 0; c < 16; ++c) { float bb = __ldg(b + c); acc0[c] = bb; acc1[c] = bb; }
#pragma unroll
    for (int kb = 0; kb < 27; kb += 9) {
        int id0[9], id1[9];
#pragma unroll
        for (int t = 0; t < 9; ++t) {
            id0[t] = __ldg(gi + (size_t)(kb + t) * n + j0);
            id1[t] = jv1 ? __ldg(gi + (size_t)(kb + t) * n + j1) : -1;
        }
        float xv0[9], xv1[9];
#pragma unroll
        for (int t = 0; t < 9; ++t) {
            xv0[t] = (id0[t] >= 0) ? __ldg(x + id0[t]) : 0.f;
            xv1[t] = (id1[t] >= 0) ? __ldg(x + id1[t]) : 0.f;
        }
#pragma unroll
        for (int t = 0; t < 9; ++t) {
#pragma unroll
            for (int c = 0; c < 16; ++c) {
                acc0[c] += xv0[t] * Ws[(kb + t) * 16 + c];
                acc1[c] += xv1[t] * Ws[(kb + t) * 16 + c];
            }
        }
    }
    {
        float4* o4 = (float4*)(out + (size_t)j0 * 16);
        float4* c4 = (float4*)(cache + (size_t)j0 * 16);
#pragma unroll
        for (int r = 0; r < 4; ++r) {
            float4 v = make_float4(fmaxf(acc0[4*r], 0.f), fmaxf(acc0[4*r+1], 0.f),
                                   fmaxf(acc0[4*r+2], 0.f), fmaxf(acc0[4*r+3], 0.f));
            o4[r] = v; c4[r] = v;
        }
    }
    if (jv1) {
        float4* o4 = (float4*)(out + (size_t)j1 * 16);
        float4* c4 = (float4*)(cache + (size_t)j1 * 16);
#pragma unroll
        for (int r = 0; r < 4; ++r) {
            float4 v = make_float4(fmaxf(acc1[4*r], 0.f), fmaxf(acc1[4*r+1], 0.f),
                                   fmaxf(acc1[4*r+2], 0.f), fmaxf(acc1[4*r+3], 0.f));
            o4[r] = v; c4[r] = v;
        }
    }
}

// ====== conv 16->16 (K=27): FOUR output rows per thread =================
// Per cc: 4 broadcast LDS.128 serve 16 FFMA2 (4 rows). X loaded in half-row
// chunks (2 float4/row) to cap registers under the (256,2) 128-reg budget.
__global__ __launch_bounds__(256, 2) void conv16_16j4(const float* __restrict__ x,
        const float* __restrict__ W, const int* __restrict__ gi,
        const float* __restrict__ b, float* __restrict__ out, int n) {
    __shared__ float4 Ws4[27 * 64];          // 27 KB
    const float4* Wg = (const float4*)W;
    for (int t = threadIdx.x; t < 27 * 64; t += 256) Ws4[t] = Wg[t];
    __syncthreads();
    const ulonglong2* Wu = (const ulonglong2*)Ws4;
    const int tid = threadIdx.x;
    int j[4];
    j[0] = blockIdx.x * 1024 + tid;
    j[1] = j[0] + 256; j[2] = j[0] + 512; j[3] = j[0] + 768;

    u64 acc[32];                              // 8 u64 per row
    {
        const float4* b4 = (const float4*)b;
#pragma unroll
        for (int r = 0; r < 4; ++r) {
            float4 bb = __ldg(b4 + r);
            u64 lo = packf2(bb.x, bb.y), hi = packf2(bb.z, bb.w);
#pragma unroll
            for (int o = 0; o < 4; ++o) { acc[o*8 + 2*r] = lo; acc[o*8 + 2*r + 1] = hi; }
        }
    }
    int a[4];
#pragma unroll
    for (int o = 0; o < 4; ++o) a[o] = (j[o] < n) ? __ldg(gi + j[o]) : -1;

    for (int k = 0; k < 27; ++k) {
        int i[4];
#pragma unroll
        for (int o = 0; o < 4; ++o) {
            i[o] = a[o];
            a[o] = (k < 26 && j[o] < n) ? __ldg(gi + (size_t)(k + 1) * n + j[o]) : -1;
        }
        if (!__ballot_sync(0xffffffffu, (i[0] >= 0) | (i[1] >= 0) | (i[2] >= 0) | (i[3] >= 0)))
            continue;
        const ulonglong2* Wk = Wu + (size_t)k * 64;
#pragma unroll
        for (int h = 0; h < 2; ++h) {         // input-channel halves (8 cc each)
            float4 X[4][2];
#pragma unroll
            for (int o = 0; o < 4; ++o) {
                const float4* xr = (const float4*)(x + (size_t)(i[o] < 0 ? 0 : i[o]) * 16) + h * 2;
#pragma unroll
                for (int q = 0; q < 2; ++q)
                    X[o][q] = (i[o] >= 0) ? __ldg(xr + q) : make_float4(0.f, 0.f, 0.f, 0.f);
            }
#pragma unroll
            for (int q = 0; q < 2; ++q) {
#pragma unroll
                for (int s = 0; s < 4; ++s) {
                    const int cc = h * 8 + q * 4 + s;
                    u64 xx[4];
#pragma unroll
                    for (int o = 0; o < 4; ++o) {
                        float xs = (s == 0) ? X[o][q].x : (s == 1) ? X[o][q].y
                                 : (s == 2) ? X[o][q].z : X[o][q].w;
                        xx[o] = bcast2(xs);
                    }
#pragma unroll
                    for (int r = 0; r < 4; ++r) {
                        ulonglong2 wp = Wk[cc * 4 + r];
#pragma unroll
                        for (int o = 0; o < 4; ++o) {
                            ffma2(acc[o*8 + 2*r],     xx[o], wp.x);
                            ffma2(acc[o*8 + 2*r + 1], xx[o], wp.y);
                        }
                    }
                }
            }
        }
    }
#pragma unroll
    for (int o = 0; o < 4; ++o) {
        if (j[o] >= n) continue;
        const u64* ap = acc + o * 8;
        float4* o4 = (float4*)(out + (size_t)j[o] * 16);
#pragma unroll
        for (int r = 0; r < 4; ++r) {
            F2U a0u, a1u; a0u.u = ap[2*r]; a1u.u = ap[2*r+1];
            o4[r] = make_float4(fmaxf(a0u.f.x, 0.f), fmaxf(a0u.f.y, 0.f),
                                fmaxf(a1u.f.x, 0.f), fmaxf(a1u.f.y, 0.f));
        }
    }
}

// ====== conv 16->32 (K=8, downsample): two output rows per thread (R12) =
__global__ __launch_bounds__(256, 2) void conv16_32j2(const float* __restrict__ x,
        const float* __restrict__ W, const int* __restrict__ gi,
        const float* __restrict__ b, float* __restrict__ out, int n) {
    __shared__ float4 Ws4[8 * 128];          // 16 KB
    const float4* Wg = (const float4*)W;
    for (int t = threadIdx.x; t < 8 * 128; t += 256) Ws4[t] = Wg[t];
    __syncthreads();
    const ulonglong2* Wu = (const ulonglong2*)Ws4;
    const int tid = threadIdx.x;
    const int j0 = blockIdx.x * 512 + tid;
    const int j1 = j0 + 256;
    const bool jv0 = j0 < n, jv1 = j1 < n;

    u64 acc[32];
    {
        const float4* b4 = (const float4*)b;
#pragma unroll
        for (int r = 0; r < 8; ++r) {
            float4 bb = __ldg(b4 + r);
            u64 lo = packf2(bb.x, bb.y), hi = packf2(bb.z, bb.w);
            acc[2*r] = lo; acc[2*r+1] = hi;
            acc[16 + 2*r] = lo; acc[16 + 2*r+1] = hi;
        }
    }
    int a0 = jv0 ? __ldg(gi + j0) : -1;
    int a1 = jv1 ? __ldg(gi + j1) : -1;
    for (int k = 0; k < 8; ++k) {
        const int i0 = a0, i1 = a1;
        a0 = (k < 7 && jv0) ? __ldg(gi + (size_t)(k + 1) * n + j0) : -1;
        a1 = (k < 7 && jv1) ? __ldg(gi + (size_t)(k + 1) * n + j1) : -1;
        if (!__ballot_sync(0xffffffffu, (i0 >= 0) || (i1 >= 0))) continue;
        const float4* xr0 = (const float4*)(x + (size_t)(i0 < 0 ? 0 : i0) * 16);
        const float4* xr1 = (const float4*)(x + (size_t)(i1 < 0 ? 0 : i1) * 16);
        float4 X0[4], X1[4];
#pragma unroll
        for (int q = 0; q < 4; ++q) {
            X0[q] = (i0 >= 0) ? __ldg(xr0 + q) : make_float4(0.f, 0.f, 0.f, 0.f);
            X1[q] = (i1 >= 0) ? __ldg(xr1 + q) : make_float4(0.f, 0.f, 0.f, 0.f);
        }
        const ulonglong2* Wk = Wu + (size_t)k * 128;
#pragma unroll
        for (int q = 0; q < 4; ++q) {
            float xs0[4] = {X0[q].x, X0[q].y, X0[q].z, X0[q].w};
            float xs1[4] = {X1[q].x, X1[q].y, X1[q].z, X1[q].w};
#pragma unroll
            for (int s = 0; s < 4; ++s) {
                int cc = q * 4 + s;
                u64 xx0 = bcast2(xs0[s]);
                u64 xx1 = bcast2(xs1[s]);
#pragma unroll
                for (int r = 0; r < 8; ++r) {
                    ulonglong2 wp = Wk[cc * 8 + r];
                    ffma2(acc[2*r],          xx0, wp.x);
                    ffma2(acc[2*r + 1],      xx0, wp.y);
                    ffma2(acc[16 + 2*r],     xx1, wp.x);
                    ffma2(acc[16 + 2*r + 1], xx1, wp.y);
                }
            }
        }
    }
#pragma unroll
    for (int o = 0; o < 2; ++o) {
        const int j = o ? j1 : j0;
        if (j >= n) continue;
        const u64* a = acc + o * 16;
        float4* o4 = (float4*)(out + (size_t)j * 32);
#pragma unroll
        for (int r = 0; r < 8; ++r) {
            F2U a0u, a1u; a0u.u = a[2*r]; a1u.u = a[2*r+1];
            o4[r] = make_float4(fmaxf(a0u.f.x, 0.f), fmaxf(a0u.f.y, 0.f),
                                fmaxf(a1u.f.x, 0.f), fmaxf(a1u.f.y, 0.f));
        }
    }
}

// ====== conv 32->32 (K=27): two rows/thread, 2 CTAs/SM (R13 winner) =====
template <int EPI>   // 0 = bias+relu, 1 = bias+residual, 2 = bias only
__global__ __launch_bounds__(256, 2) void conv32_32j2(const float* __restrict__ x,
        const float* __restrict__ W, const int* __restrict__ gi,
        const float* __restrict__ b, const float* __restrict__ skip,
        float* __restrict__ out, int n) {
    extern __shared__ float4 Ws4[];          // 27 * 256 float4 = 108 KB
    const float4* Wg = (const float4*)W;
    for (int t = threadIdx.x; t < 27 * 256; t += 256) Ws4[t] = Wg[t];
    __syncthreads();
    const ulonglong2* Wu = (const ulonglong2*)Ws4;
    const int tid = threadIdx.x;
    const int j0 = blockIdx.x * 512 + tid;
    const int j1 = j0 + 256;
    const bool jv0 = j0 < n, jv1 = j1 < n;

    u64 acc[32];                              // [0..15] row j0, [16..31] row j1
    {
        const float4* b4 = (const float4*)b;
#pragma unroll
        for (int r = 0; r < 8; ++r) {
            float4 bb = __ldg(b4 + r);
            u64 lo = packf2(bb.x, bb.y), hi = packf2(bb.z, bb.w);
            acc[2*r] = lo; acc[2*r+1] = hi;
            acc[16 + 2*r] = lo; acc[16 + 2*r+1] = hi;
        }
    }
    int a0 = jv0 ? __ldg(gi + j0) : -1;
    int a1 = jv1 ? __ldg(gi + j1) : -1;
    for (int k = 0; k < 27; ++k) {
        const int i0 = a0, i1 = a1;
        a0 = (k < 26 && jv0) ? __ldg(gi + (size_t)(k + 1) * n + j0) : -1;
        a1 = (k < 26 && jv1) ? __ldg(gi + (size_t)(k + 1) * n + j1) : -1;
        if (!__ballot_sync(0xffffffffu, (i0 >= 0) || (i1 >= 0))) continue;
        const float4* xr0 = (const float4*)(x + (size_t)(i0 < 0 ? 0 : i0) * 32);
        const float4* xr1 = (const float4*)(x + (size_t)(i1 < 0 ? 0 : i1) * 32);
        const ulonglong2* Wk = Wu + (size_t)k * 256;
#pragma unroll
        for (int h = 0; h < 2; ++h) {         // input-channel halves keep regs low
            float4 X0[4], X1[4];
#pragma unroll
            for (int q = 0; q < 4; ++q) {
                X0[q] = (i0 >= 0) ? __ldg(xr0 + h * 4 + q) : make_float4(0.f, 0.f, 0.f, 0.f);
                X1[q] = (i1 >= 0) ? __ldg(xr1 + h * 4 + q) : make_float4(0.f, 0.f, 0.f, 0.f);
            }
#pragma unroll
            for (int q = 0; q < 4; ++q) {
                float xs0[4] = {X0[q].x, X0[q].y, X0[q].z, X0[q].w};
                float xs1[4] = {X1[q].x, X1[q].y, X1[q].z, X1[q].w};
#pragma unroll
                for (int s = 0; s < 4; ++s) {
                    int cc = h * 16 + q * 4 + s;
                    u64 xx0 = bcast2(xs0[s]);
                    u64 xx1 = bcast2(xs1[s]);
#pragma unroll
                    for (int r = 0; r < 8; ++r) {
                        ulonglong2 wp = Wk[cc * 8 + r];
                        ffma2(acc[2*r],          xx0, wp.x);
                        ffma2(acc[2*r + 1],      xx0, wp.y);
                        ffma2(acc[16 + 2*r],     xx1, wp.x);
                        ffma2(acc[16 + 2*r + 1], xx1, wp.y);
                    }
                }
            }
        }
    }
#pragma unroll
    for (int o = 0; o < 2; ++o) {
        const int j = o ? j1 : j0;
        if (j >= n) continue;
        const u64* a = acc + o * 16;
        float4* o4 = (float4*)(out + (size_t)j * 32);
        const float4* s4 = (EPI == 1) ? (const float4*)(skip + (size_t)j * 32) : nullptr;
#pragma unroll
        for (int r = 0; r < 8; ++r) {
            F2U a0u, a1u; a0u.u = a[2*r]; a1u.u = a[2*r+1];
            float4 v = make_float4(a0u.f.x, a0u.f.y, a1u.f.x, a1u.f.y);
            if (EPI == 0) {
                v.x = fmaxf(v.x, 0.f); v.y = fmaxf(v.y, 0.f);
                v.z = fmaxf(v.z, 0.f); v.w = fmaxf(v.w, 0.f);
            }
            if (EPI == 1) {
                float4 sv = __ldg(s4 + r);
                v.x += sv.x; v.y += sv.y; v.z += sv.z; v.w += sv.w;
            }
            o4[r] = v;
        }
    }
}

// ---------------- host orchestration ----------------
extern "C" void kernel_launch(void* const* d_in, const int* in_sizes, int n_in,
                              void* d_out, int out_size) {
    const float* in_feats = (const float*)d_in[0];
    const float* W_first  = (const float*)d_in[1];
    const float* b_first  = (const float*)d_in[2];
    const float* W_pre    = (const float*)d_in[3];
    const float* b_pre    = (const float*)d_in[4];
    const float* W_down   = (const float*)d_in[5];
    const float* b_down   = (const float*)d_in[6];
    const float* W_r0     = (const float*)d_in[7];
    const float* b_r0     = (const float*)d_in[8];
    const float* W_r1     = (const float*)d_in[9];
    const float* b_r1     = (const float*)d_in[10];
    const float* W_fin    = (const float*)d_in[11];
    const float* b_fin    = (const float*)d_in[12];
    const int* km0_in  = (const int*)d_in[13];
    const int* km0_out = (const int*)d_in[14];
    const int* kmd_in  = (const int*)d_in[15];
    const int* kmd_out = (const int*)d_in[16];
    const int* km1_in  = (const int*)d_in[17];
    const int* km1_out = (const int*)d_in[18];

    const int n0 = in_sizes[0];
    const int P0 = in_sizes[13] / 27;
    const int Pd = in_sizes[15] / 8;
    const int P1 = in_sizes[17] / 27;
    const int n1 = (out_size - n0 * 16) / 32;

    float* out_fin    = (float*)d_out;
    float* out_cached = (float*)d_out + (size_t)n1 * 32;

    float *x0, *x1, *x2, *r0, *r1;
    int *gi0, *gid, *gi1;
    cudaGetSymbolAddress((void**)&x0, g_x0);
    cudaGetSymbolAddress((void**)&x1, g_x1);
    cudaGetSymbolAddress((void**)&x2, g_x2);
    cudaGetSymbolAddress((void**)&r0, g_r0);
    cudaGetSymbolAddress((void**)&r1, g_r1);
    cudaGetSymbolAddress((void**)&gi0, g_gi0);
    cudaGetSymbolAddress((void**)&gid, g_gid);
    cudaGetSymbolAddress((void**)&gi1, g_gi1);

    const int SMEM32 = 27 * 256 * sizeof(float4);  // 110592 B
    static bool attr_done = false;
    if (!attr_done) {
        cudaFuncSetAttribute(conv32_32j2<0>, cudaFuncAttributeMaxDynamicSharedMemorySize, SMEM32);
        cudaFuncSetAttribute(conv32_32j2<1>, cudaFuncAttributeMaxDynamicSharedMemorySize, SMEM32);
        cudaFuncSetAttribute(conv32_32j2<2>, cudaFuncAttributeMaxDynamicSharedMemorySize, SMEM32);
        attr_done = true;
    }

    auto ceil_div = [](int a, int b) { return (a + b - 1) / b; };
    const int T = 256;

    // ---- build inverse maps ----
    cudaMemsetAsync(gi0, 0xFF, (size_t)27 * n0 * sizeof(int), 0);
    cudaMemsetAsync(gid, 0xFF, (size_t)8 * n1 * sizeof(int), 0);
    cudaMemsetAsync(gi1, 0xFF, (size_t)27 * n1 * sizeof(int), 0);
    {
        dim3 g0(ceil_div(P0, T), 27);
        build_gi<<<g0, T>>>(km0_in, km0_out, gi0, P0, n0);
        dim3 gd(ceil_div(Pd, T), 8);
        build_gi<<<gd, T>>>(kmd_in, kmd_out, gid, Pd, n1);
        dim3 g1(ceil_div(P1, T), 27);
        build_gi<<<g1, T>>>(km1_in, km1_out, gi1, P1, n1);
    }

    conv1_16j2<<<ceil_div(n0, 512), T>>>(in_feats, W_first, gi0, b_first, x0, out_cached, n0);
    conv16_16j4<<<ceil_div(n0, 1024), T>>>(x0, W_pre, gi0, b_pre, x1, n0);
    conv16_32j2<<<ceil_div(n1, 512), T>>>(x1, W_down, gid, b_down, x2, n1);

    const int gb = ceil_div(n1, 512);
    conv32_32j2<0><<<gb, 256, SMEM32>>>(x2, W_r0, gi1, b_r0, nullptr, r0, n1);
    conv32_32j2<1><<<gb, 256, SMEM32>>>(r0, W_r1, gi1, b_r1, x2, r1, n1);
    conv32_32j2<2><<<gb, 256, SMEM32>>>(r1, W_fin, gi1, b_fin, nullptr, out_fin, n1);
}